// round 11
// baseline (speedup 1.0000x reference)
#include <cuda_runtime.h>
#include <cuda_fp16.h>
#include <cstdint>
#include <math.h>

// Problem constants
#define D_MODEL   1024
#define NUM_HEADS 16
#define DK        64
#define BATCH     2
#define SEQ       2048
#define NROWS     (BATCH * SEQ)      // 4096
#define NX        (NROWS * D_MODEL)  // 4194304
#define NW        (D_MODEL * D_MODEL)// 1048576

// ---------------------------------------------------------------------------
// Scratch (device globals: allocation-free rule)
// fp16 asymmetric split: "A" operands stored single, "B" operands hi+lo.
// ---------------------------------------------------------------------------
__device__ __half g_xh[NX];                        // x single fp16
__device__ __half g_Wh[4 * NW], g_Wl[4 * NW];      // Wq,Wk,Wv,Wo hi/lo
__device__ __half g_Qh[NX];                        // [b][h][s][d], pre-scaled 0.125
__device__ __half g_Kh[NX], g_Kl[NX];
__device__ __half g_Vh[NX], g_Vl[NX];
__device__ __half g_AOh[NX];                       // attn out single [b][s][h*64+d]

// ---------------------------------------------------------------------------
// PTX helpers (plain sm_100-safe: ldmatrix, mma.sync f16, cp.async)
// ---------------------------------------------------------------------------
__device__ __forceinline__ uint32_t smem_to_u32(const void* p) {
    uint32_t a;
    asm("{ .reg .u64 t; cvta.to.shared.u64 t, %1; cvt.u32.u64 %0, t; }" : "=r"(a) : "l"(p));
    return a;
}
__device__ __forceinline__ void ldsm_x4(uint32_t* r, uint32_t addr) {
    asm volatile("ldmatrix.sync.aligned.m8n8.x4.shared.b16 {%0,%1,%2,%3}, [%4];"
        : "=r"(r[0]), "=r"(r[1]), "=r"(r[2]), "=r"(r[3]) : "r"(addr));
}
__device__ __forceinline__ void ldsm_x4_t(uint32_t* r, uint32_t addr) {
    asm volatile("ldmatrix.sync.aligned.m8n8.x4.trans.shared.b16 {%0,%1,%2,%3}, [%4];"
        : "=r"(r[0]), "=r"(r[1]), "=r"(r[2]), "=r"(r[3]) : "r"(addr));
}
__device__ __forceinline__ void mma_f16(float* d, const uint32_t* a, uint32_t b0, uint32_t b1) {
    asm volatile("mma.sync.aligned.m16n8k16.row.col.f32.f16.f16.f32 "
        "{%0,%1,%2,%3}, {%4,%5,%6,%7}, {%8,%9}, {%0,%1,%2,%3};"
        : "+f"(d[0]), "+f"(d[1]), "+f"(d[2]), "+f"(d[3])
        : "r"(a[0]), "r"(a[1]), "r"(a[2]), "r"(a[3]), "r"(b0), "r"(b1));
}
__device__ __forceinline__ void cp16(uint32_t dst, const void* src) {
    asm volatile("cp.async.cg.shared.global [%0], [%1], 16;" :: "r"(dst), "l"(src));
}
__device__ __forceinline__ void cp4(uint32_t dst, const void* src) {
    asm volatile("cp.async.ca.shared.global [%0], [%1], 4;" :: "r"(dst), "l"(src));
}
#define CP_COMMIT() asm volatile("cp.async.commit_group;" ::: "memory")
#define CP_WAIT1()  asm volatile("cp.async.wait_group 1;" ::: "memory")
#define CP_WAIT0()  asm volatile("cp.async.wait_group 0;" ::: "memory")

__device__ __forceinline__ uint32_t pack_h(__half a, __half b) {
    __half2 t = __halves2half2(a, b);
    return *(uint32_t*)&t;
}

// ---------------------------------------------------------------------------
// Pre-pass: convert x (single fp16) + 4 weights (fp16 hi/lo)
// ---------------------------------------------------------------------------
__global__ __launch_bounds__(256) void cvt_all(
    const float* __restrict__ x,  const float* __restrict__ wq,
    const float* __restrict__ wk, const float* __restrict__ wv,
    const float* __restrict__ wo)
{
    int y = blockIdx.y;
    const float* s = (y == 0) ? x : (y == 1) ? wq : (y == 2) ? wk : (y == 3) ? wv : wo;
    __half* dh = (y == 0) ? g_xh : g_Wh + (size_t)(y - 1) * NW;
    __half* dl = (y == 0) ? (__half*)nullptr : g_Wl + (size_t)(y - 1) * NW;
    size_t n = (y == 0) ? (size_t)NX : (size_t)NW;
    size_t stride = (size_t)gridDim.x * 256 * 4;
    for (size_t i = ((size_t)blockIdx.x * 256 + threadIdx.x) * 4; i < n; i += stride) {
        float4 v = *(const float4*)(s + i);
        float f[4] = {v.x, v.y, v.z, v.w};
        __half h[4];
#pragma unroll
        for (int e = 0; e < 4; e++) h[e] = __float2half_rn(f[e]);
        *(uint2*)(dh + i) = make_uint2(pack_h(h[0], h[1]), pack_h(h[2], h[3]));
        if (y != 0) {
            __half l[4];
#pragma unroll
            for (int e = 0; e < 4; e++)
                l[e] = __float2half_rn(f[e] - __half2float(h[e]));
            *(uint2*)(dl + i) = make_uint2(pack_h(l[0], l[1]), pack_h(l[2], l[3]));
        }
    }
}

// ---------------------------------------------------------------------------
// fp16 asymmetric-split GEMM: C = A(single) @ (Wh + Wl)^T, 2 mma per tile-k16.
// CTA 128x128, 8 warps (2m x 4n), k-stage 32, cp.async 3-stage (wait_group 1),
// 1 sync/stage, 2 CTA/SM.
// MODE 0: QKV (z selects W; epilogue: Q -> single (x0.125), K/V -> hi+lo)
// MODE 1: O-proj (A = g_AOh; fp32 epilogue to out)
// ---------------------------------------------------------------------------
#define SSTR 40                        // smem row stride in halves
#define SSTRB 80
#define STAGE_B   (128 * SSTR * 2)     // 10240 bytes per array per stage
#define NSTAGES   3
#define GEMM_SMEM (9 * STAGE_B)        // 92160: A(3 stages) + Bh(3) + Bl(3)
#define NST       (D_MODEL / 32)       // 32 k-stages

template<int MODE>
__global__ __launch_bounds__(256, 2) void gemm_mma(float* __restrict__ outp)
{
    extern __shared__ __half ds[];

    int tid = threadIdx.x;
    int wid = tid >> 5, lane = tid & 31;
    int wm = wid & 1, wn = wid >> 1;
    int rowBase = blockIdx.y * 128, colBase = blockIdx.x * 128;

    const __half *Ag, *Bhg, *Blg;
    if (MODE == 0) {
        int z = blockIdx.z;
        Ag = g_xh;
        Bhg = g_Wh + (size_t)z * NW;  Blg = g_Wl + (size_t)z * NW;
    } else {
        Ag = g_AOh;
        Bhg = g_Wh + 3ull * NW;       Blg = g_Wl + 3ull * NW;
    }
    Ag  += (size_t)rowBase * D_MODEL;
    Bhg += (size_t)colBase * D_MODEL;  Blg += (size_t)colBase * D_MODEL;

    uint32_t u0  = smem_to_u32(ds);
    uint32_t uA  = u0;
    uint32_t uBh = u0 + NSTAGES * STAGE_B;
    uint32_t uBl = u0 + 2 * NSTAGES * STAGE_B;

    float acc[4][4][4];
#pragma unroll
    for (int i = 0; i < 4; i++)
#pragma unroll
        for (int j = 0; j < 4; j++)
#pragma unroll
            for (int c = 0; c < 4; c++) acc[i][j][c] = 0.f;

    uint32_t aOff = (uint32_t)((wm * 64 + (lane & 15)) * SSTRB + (lane >> 4) * 16);
    uint32_t bOff = (uint32_t)((wn * 32 + (lane & 7) + ((lane >> 4) & 1) * 8) * SSTRB
                               + ((lane >> 3) & 1) * 16);

    auto issue = [&](int st) {
        uint32_t sb = (uint32_t)((st % NSTAGES) * STAGE_B);
        int k0 = st * 32;
#pragma unroll
        for (int u = 0; u < 2; u++) {
            int f = tid + 256 * u;
            int row = f >> 2, seg = (f & 3) * 8;
            uint32_t so = sb + (uint32_t)(row * SSTR + seg) * 2;
            size_t g = (size_t)row * D_MODEL + k0 + seg;
            cp16(uA  + so, Ag  + g);
            cp16(uBh + so, Bhg + g);
            cp16(uBl + so, Blg + g);
        }
        CP_COMMIT();
    };

    issue(0);
    issue(1);

    for (int st = 0; st < NST; st++) {
        uint32_t sOff = (uint32_t)((st % NSTAGES) * STAGE_B);
        if (st < NST - 1) CP_WAIT1();     // stage st complete; st+1 may be in flight
        else              CP_WAIT0();
        __syncthreads();                  // all warps done with buffer (st-1)%3
        if (st + 2 < NST) issue(st + 2);  // targets buffer (st-1)%3 — safe post-barrier

#pragma unroll
        for (int ks = 0; ks < 2; ks++) {
            uint32_t kb = (uint32_t)(ks * 32);
            uint32_t bh[2][4], bl[2][4];
#pragma unroll
            for (int p = 0; p < 2; p++) {
                uint32_t o = sOff + bOff + p * 16 * SSTRB + kb;
                ldsm_x4(bh[p], uBh + o);
                ldsm_x4(bl[p], uBl + o);
            }
#pragma unroll
            for (int mt = 0; mt < 4; mt++) {
                uint32_t ah[4];
                ldsm_x4(ah, uA + sOff + aOff + mt * 16 * SSTRB + kb);
#pragma unroll
                for (int nt = 0; nt < 4; nt++) {
                    int p = nt >> 1, q = (nt & 1) * 2;
                    mma_f16(acc[mt][nt], ah, bh[p][q], bh[p][q + 1]);
                    mma_f16(acc[mt][nt], ah, bl[p][q], bl[p][q + 1]);
                }
            }
        }
    }

    // Epilogue
#pragma unroll
    for (int mt = 0; mt < 4; mt++)
#pragma unroll
        for (int nt = 0; nt < 4; nt++) {
            int row0 = rowBase + wm * 64 + mt * 16 + (lane >> 2);
            int col  = colBase + wn * 32 + nt * 8 + (lane & 3) * 2;
#pragma unroll
            for (int cp = 0; cp < 2; cp++) {
                int row = row0 + cp * 8;
                float v0 = acc[mt][nt][cp * 2], v1 = acc[mt][nt][cp * 2 + 1];
                if (MODE == 1) {
                    *(float2*)(outp + (size_t)row * D_MODEL + col) = make_float2(v0, v1);
                } else {
                    int z = blockIdx.z;
                    if (z == 0) { v0 *= 0.125f; v1 *= 0.125f; }
                    int b = row >> 11, s = row & 2047;
                    int h = col >> 6, d = col & 63;
                    size_t idx = ((size_t)(b * NUM_HEADS + h) * SEQ + s) * DK + d;
                    __half h0 = __float2half_rn(v0), h1 = __float2half_rn(v1);
                    __half* dh = (z == 0) ? g_Qh : (z == 1) ? g_Kh : g_Vh;
                    *(uint32_t*)(dh + idx) = pack_h(h0, h1);
                    if (z != 0) {
                        __half* dl = (z == 1) ? g_Kl : g_Vl;
                        __half l0 = __float2half_rn(v0 - __half2float(h0));
                        __half l1 = __float2half_rn(v1 - __half2float(h1));
                        *(uint32_t*)(dl + idx) = pack_h(l0, l1);
                    }
                }
            }
        }
}

// ---------------------------------------------------------------------------
// Flash attention, fp16 asymmetric split, cp.async 3-stage K/V pipeline:
//   S = Qh*(Kh+Kl)  (Q single, 2 mma);  O += Ph*(Vh+Vl)  (P single, 2 mma)
// CTA: 128 q rows, 8 warps, K-tile 64, 1 sync/tile, wait_group 1.
// ---------------------------------------------------------------------------
#define FSTR  72                      // smem row stride (halves)
#define FSTRB 144
#define FQ_ELE (128 * FSTR)           // 9216 halves
#define FQB    (FQ_ELE * 2)           // 18432 bytes
#define FK_ELE (64 * FSTR)            // 4608 halves
#define FKB    (FK_ELE * 2)           // 9216 bytes per array per stage
#define FNS    3
#define FL_SMEM (FQB + 4 * FNS * FKB) // 129024 bytes
#define NKT    (SEQ / 64)             // 32 k-tiles

__global__ __launch_bounds__(256) void flash_mma(const int* __restrict__ am)
{
    extern __shared__ __half sb[];
    __shared__ int msk[FNS][64];

    int tid = threadIdx.x;
    int wid = tid >> 5, lane = tid & 31;
    int g = lane >> 2, tig = lane & 3;
    int q0 = blockIdx.x * 128;
    int h  = blockIdx.y;
    int b  = blockIdx.z;

    size_t hoff = ((size_t)(b * NUM_HEADS + h) * SEQ) * DK;

    uint32_t uB  = smem_to_u32(sb);
    uint32_t uQ  = uB;
    uint32_t uKh = uB + FQB;
    uint32_t uKl = uKh + FNS * FKB;
    uint32_t uVh = uKh + 2 * FNS * FKB;
    uint32_t uVl = uKh + 3 * FNS * FKB;
    uint32_t umsk = smem_to_u32(msk);

    const __half* Khg = g_Kh + hoff;
    const __half* Klg = g_Kl + hoff;
    const __half* Vhg = g_Vh + hoff;
    const __half* Vlg = g_Vl + hoff;

    auto issueKV = [&](int kt) {
        uint32_t sbyte = (uint32_t)((kt % FNS) * FKB);
        size_t k0d = (size_t)(kt * 64) * DK;
#pragma unroll
        for (int u = 0; u < 2; u++) {
            int f = tid + 256 * u;
            int row = f >> 3, seg = (f & 7) * 8;
            uint32_t so = sbyte + (uint32_t)(row * FSTR + seg) * 2;
            size_t go = k0d + (size_t)row * DK + seg;
            cp16(uKh + so, Khg + go);
            cp16(uKl + so, Klg + go);
            cp16(uVh + so, Vhg + go);
            cp16(uVl + so, Vlg + go);
        }
        if (tid < 64)
            cp4(umsk + (uint32_t)(((kt % FNS) * 64 + tid) * 4),
                am + (size_t)b * SEQ + kt * 64 + tid);
        CP_COMMIT();
    };

    issueKV(0);
    issueKV(1);

    // Load Q (single fp16, 128 rows x 64 halves) behind the first K/V fetches.
    const __half* Qg = g_Qh + hoff + (size_t)q0 * DK;
    {
        int row = tid >> 1, seg = (tid & 1) * 32;
        *(uint4*)(sb + row * FSTR + seg)      = *(const uint4*)(Qg + (size_t)row * DK + seg);
        *(uint4*)(sb + row * FSTR + seg + 8)  = *(const uint4*)(Qg + (size_t)row * DK + seg + 8);
        *(uint4*)(sb + row * FSTR + seg + 16) = *(const uint4*)(Qg + (size_t)row * DK + seg + 16);
        *(uint4*)(sb + row * FSTR + seg + 24) = *(const uint4*)(Qg + (size_t)row * DK + seg + 24);
    }
    __syncthreads();

    uint32_t qOff = (uint32_t)((wid * 16 + (lane & 15)) * FSTRB + (lane >> 4) * 16);
    uint32_t qh[4][4];
#pragma unroll
    for (int kst = 0; kst < 4; kst++)
        ldsm_x4(qh[kst], uQ + qOff + kst * 32);

    float oacc[8][4];
#pragma unroll
    for (int nt = 0; nt < 8; nt++)
#pragma unroll
        for (int c = 0; c < 4; c++) oacc[nt][c] = 0.f;
    float mrow[2] = {-1e30f, -1e30f}, lrow[2] = {0.f, 0.f};

    uint32_t bOffK = (uint32_t)(((lane & 7) + ((lane >> 4) & 1) * 8) * FSTRB + ((lane >> 3) & 1) * 16);
    uint32_t vOff  = (uint32_t)((lane & 15) * FSTRB + (lane >> 4) * 16);

    for (int kt = 0; kt < NKT; kt++) {
        int stage = kt % FNS;
        if (kt < NKT - 1) CP_WAIT1();     // tile kt complete; kt+1 may be in flight
        else              CP_WAIT0();
        __syncthreads();                  // all warps done with buffer (kt-1)%3
        if (kt + 2 < NKT) issueKV(kt + 2);

        uint32_t skh = uKh + stage * FKB, skl = uKl + stage * FKB;
        uint32_t svh = uVh + stage * FKB, svl = uVl + stage * FKB;

        // ----- S = Qh (Kh + Kl)^T -----
        float s[8][4];
#pragma unroll
        for (int nt = 0; nt < 8; nt++)
#pragma unroll
            for (int c = 0; c < 4; c++) s[nt][c] = 0.f;

#pragma unroll
        for (int p = 0; p < 4; p++) {
#pragma unroll
            for (int kst = 0; kst < 4; kst++) {
                uint32_t kh[4], kl[4];
                uint32_t o = p * 16 * FSTRB + kst * 32 + bOffK;
                ldsm_x4(kh, skh + o);
                ldsm_x4(kl, skl + o);
                int nt0 = 2 * p, nt1 = 2 * p + 1;
                mma_f16(s[nt0], qh[kst], kh[0], kh[1]);
                mma_f16(s[nt0], qh[kst], kl[0], kl[1]);
                mma_f16(s[nt1], qh[kst], kh[2], kh[3]);
                mma_f16(s[nt1], qh[kst], kl[2], kl[3]);
            }
        }

        // ----- mask -----
#pragma unroll
        for (int nt = 0; nt < 8; nt++) {
            int c0 = nt * 8 + tig * 2;
            if (msk[stage][c0] == 0)     { s[nt][0] = -1e30f; s[nt][2] = -1e30f; }
            if (msk[stage][c0 + 1] == 0) { s[nt][1] = -1e30f; s[nt][3] = -1e30f; }
        }

        // ----- online softmax (rows g and g+8) -----
        float mx0 = -1e30f, mx1 = -1e30f;
#pragma unroll
        for (int nt = 0; nt < 8; nt++) {
            mx0 = fmaxf(mx0, fmaxf(s[nt][0], s[nt][1]));
            mx1 = fmaxf(mx1, fmaxf(s[nt][2], s[nt][3]));
        }
#pragma unroll
        for (int o = 1; o <= 2; o <<= 1) {
            mx0 = fmaxf(mx0, __shfl_xor_sync(0xffffffffu, mx0, o));
            mx1 = fmaxf(mx1, __shfl_xor_sync(0xffffffffu, mx1, o));
        }
        float mn0 = fmaxf(mrow[0], mx0), mn1 = fmaxf(mrow[1], mx1);
        float al0 = __expf(mrow[0] - mn0), al1 = __expf(mrow[1] - mn1);
        float rs0 = 0.f, rs1 = 0.f;
#pragma unroll
        for (int nt = 0; nt < 8; nt++) {
            s[nt][0] = __expf(s[nt][0] - mn0); rs0 += s[nt][0];
            s[nt][1] = __expf(s[nt][1] - mn0); rs0 += s[nt][1];
            s[nt][2] = __expf(s[nt][2] - mn1); rs1 += s[nt][2];
            s[nt][3] = __expf(s[nt][3] - mn1); rs1 += s[nt][3];
        }
#pragma unroll
        for (int o = 1; o <= 2; o <<= 1) {
            rs0 += __shfl_xor_sync(0xffffffffu, rs0, o);
            rs1 += __shfl_xor_sync(0xffffffffu, rs1, o);
        }
        lrow[0] = lrow[0] * al0 + rs0;  mrow[0] = mn0;
        lrow[1] = lrow[1] * al1 + rs1;  mrow[1] = mn1;
#pragma unroll
        for (int nt = 0; nt < 8; nt++) {
            oacc[nt][0] *= al0; oacc[nt][1] *= al0;
            oacc[nt][2] *= al1; oacc[nt][3] *= al1;
        }

        // ----- P -> single-fp16 A-fragments -----
        uint32_t pa[4][4];
#pragma unroll
        for (int kc = 0; kc < 4; kc++) {
            const float* t0 = s[2 * kc];
            const float* t1 = s[2 * kc + 1];
            pa[kc][0] = pack_h(__float2half_rn(t0[0]), __float2half_rn(t0[1]));
            pa[kc][1] = pack_h(__float2half_rn(t0[2]), __float2half_rn(t0[3]));
            pa[kc][2] = pack_h(__float2half_rn(t1[0]), __float2half_rn(t1[1]));
            pa[kc][3] = pack_h(__float2half_rn(t1[2]), __float2half_rn(t1[3]));
        }

        // ----- O += P (Vh + Vl) -----
#pragma unroll
        for (int kc = 0; kc < 4; kc++) {
            uint32_t vh[4][4], vl[4][4];
#pragma unroll
            for (int p = 0; p < 4; p++) {
                uint32_t o = kc * 16 * FSTRB + p * 32 + vOff;
                ldsm_x4_t(vh[p], svh + o);
                ldsm_x4_t(vl[p], svl + o);
            }
#pragma unroll
            for (int nt = 0; nt < 8; nt++) {
                int p = nt >> 1, q = (nt & 1) * 2;
                mma_f16(oacc[nt], pa[kc], vh[p][q], vh[p][q + 1]);
                mma_f16(oacc[nt], pa[kc], vl[p][q], vl[p][q + 1]);
            }
        }
    }

    // ----- epilogue: normalize, single-fp16 write to g_AOh -----
    float inv0 = (lrow[0] > 0.f) ? (1.f / lrow[0]) : 0.f;
    float inv1 = (lrow[1] > 0.f) ? (1.f / lrow[1]) : 0.f;
    int r0 = q0 + wid * 16 + g;
    int r1 = r0 + 8;
#pragma unroll
    for (int nt = 0; nt < 8; nt++) {
        int d0 = nt * 8 + tig * 2;
        size_t i0 = ((size_t)b * SEQ + r0) * D_MODEL + h * DK + d0;
        size_t i1 = ((size_t)b * SEQ + r1) * D_MODEL + h * DK + d0;
        *(uint32_t*)(g_AOh + i0) = pack_h(__float2half_rn(oacc[nt][0] * inv0),
                                          __float2half_rn(oacc[nt][1] * inv0));
        *(uint32_t*)(g_AOh + i1) = pack_h(__float2half_rn(oacc[nt][2] * inv1),
                                          __float2half_rn(oacc[nt][3] * inv1));
    }
}

// ---------------------------------------------------------------------------
// Launch
// ---------------------------------------------------------------------------
extern "C" void kernel_launch(void* const* d_in, const int* in_sizes, int n_in,
                              void* d_out, int out_size)
{
    const float* x  = (const float*)d_in[0];
    const int*   am = (const int*)d_in[1];
    const float* Wq = (const float*)d_in[2];
    const float* Wk = (const float*)d_in[3];
    const float* Wv = (const float*)d_in[4];
    const float* Wo = (const float*)d_in[5];
    float* out = (float*)d_out;

    cudaFuncSetAttribute(gemm_mma<0>, cudaFuncAttributeMaxDynamicSharedMemorySize, GEMM_SMEM);
    cudaFuncSetAttribute(gemm_mma<1>, cudaFuncAttributeMaxDynamicSharedMemorySize, GEMM_SMEM);
    cudaFuncSetAttribute(flash_mma, cudaFuncAttributeMaxDynamicSharedMemorySize, FL_SMEM);

    dim3 gc(1024, 5);
    cvt_all<<<gc, 256>>>(x, Wq, Wk, Wv, Wo);

    dim3 gq(D_MODEL / 128, NROWS / 128, 3);     // (8, 32, 3)
    gemm_mma<0><<<gq, 256, GEMM_SMEM>>>(nullptr);

    dim3 ga(SEQ / 128, NUM_HEADS, BATCH);       // (16, 16, 2)
    flash_mma<<<ga, 256, FL_SMEM>>>(am);

    dim3 go(D_MODEL / 128, NROWS / 128, 1);     // (8, 32)
    gemm_mma<1><<<go, 256, GEMM_SMEM>>>(out);
}

// round 13
// speedup vs baseline: 1.0517x; 1.0517x over previous
#include <cuda_runtime.h>
#include <cuda_fp16.h>
#include <cstdint>
#include <math.h>

// Problem constants
#define D_MODEL   1024
#define NUM_HEADS 16
#define DK        64
#define BATCH     2
#define SEQ       2048
#define NROWS     (BATCH * SEQ)      // 4096
#define NX        (NROWS * D_MODEL)  // 4194304
#define NW        (D_MODEL * D_MODEL)// 1048576

// ---------------------------------------------------------------------------
// Scratch (device globals: allocation-free rule)
// fp16 asymmetric split: "A" operands stored single, "B" operands hi+lo.
// ---------------------------------------------------------------------------
__device__ __half g_xh[NX];                        // x single fp16
__device__ __half g_Wh[4 * NW], g_Wl[4 * NW];      // Wq,Wk,Wv,Wo hi/lo
__device__ __half g_Qh[NX];                        // [b][h][s][d], pre-scaled 0.125
__device__ __half g_Kh[NX], g_Kl[NX];
__device__ __half g_Vh[NX], g_Vl[NX];
__device__ __half g_AOh[NX];                       // attn out single [b][s][h*64+d]

// ---------------------------------------------------------------------------
// PTX helpers (plain sm_100-safe: ldmatrix, mma.sync f16, cp.async)
// ---------------------------------------------------------------------------
__device__ __forceinline__ uint32_t smem_to_u32(const void* p) {
    uint32_t a;
    asm("{ .reg .u64 t; cvta.to.shared.u64 t, %1; cvt.u32.u64 %0, t; }" : "=r"(a) : "l"(p));
    return a;
}
__device__ __forceinline__ void ldsm_x4(uint32_t* r, uint32_t addr) {
    asm volatile("ldmatrix.sync.aligned.m8n8.x4.shared.b16 {%0,%1,%2,%3}, [%4];"
        : "=r"(r[0]), "=r"(r[1]), "=r"(r[2]), "=r"(r[3]) : "r"(addr));
}
__device__ __forceinline__ void ldsm_x4_t(uint32_t* r, uint32_t addr) {
    asm volatile("ldmatrix.sync.aligned.m8n8.x4.trans.shared.b16 {%0,%1,%2,%3}, [%4];"
        : "=r"(r[0]), "=r"(r[1]), "=r"(r[2]), "=r"(r[3]) : "r"(addr));
}
__device__ __forceinline__ void mma_f16(float* d, const uint32_t* a, uint32_t b0, uint32_t b1) {
    asm volatile("mma.sync.aligned.m16n8k16.row.col.f32.f16.f16.f32 "
        "{%0,%1,%2,%3}, {%4,%5,%6,%7}, {%8,%9}, {%0,%1,%2,%3};"
        : "+f"(d[0]), "+f"(d[1]), "+f"(d[2]), "+f"(d[3])
        : "r"(a[0]), "r"(a[1]), "r"(a[2]), "r"(a[3]), "r"(b0), "r"(b1));
}
__device__ __forceinline__ void cp16(uint32_t dst, const void* src) {
    asm volatile("cp.async.cg.shared.global [%0], [%1], 16;" :: "r"(dst), "l"(src));
}
__device__ __forceinline__ void cp4(uint32_t dst, const void* src) {
    asm volatile("cp.async.ca.shared.global [%0], [%1], 4;" :: "r"(dst), "l"(src));
}
#define CP_COMMIT() asm volatile("cp.async.commit_group;" ::: "memory")
#define CP_WAIT0()  asm volatile("cp.async.wait_group 0;" ::: "memory")

__device__ __forceinline__ uint32_t pack_h(__half a, __half b) {
    __half2 t = __halves2half2(a, b);
    return *(uint32_t*)&t;
}

// ---------------------------------------------------------------------------
// Pre-pass: convert x (single fp16) + 4 weights (fp16 hi/lo)
// ---------------------------------------------------------------------------
__global__ __launch_bounds__(256) void cvt_all(
    const float* __restrict__ x,  const float* __restrict__ wq,
    const float* __restrict__ wk, const float* __restrict__ wv,
    const float* __restrict__ wo)
{
    int y = blockIdx.y;
    const float* s = (y == 0) ? x : (y == 1) ? wq : (y == 2) ? wk : (y == 3) ? wv : wo;
    __half* dh = (y == 0) ? g_xh : g_Wh + (size_t)(y - 1) * NW;
    __half* dl = (y == 0) ? (__half*)nullptr : g_Wl + (size_t)(y - 1) * NW;
    size_t n = (y == 0) ? (size_t)NX : (size_t)NW;
    size_t stride = (size_t)gridDim.x * 256 * 4;
    for (size_t i = ((size_t)blockIdx.x * 256 + threadIdx.x) * 4; i < n; i += stride) {
        float4 v = *(const float4*)(s + i);
        float f[4] = {v.x, v.y, v.z, v.w};
        __half h[4];
#pragma unroll
        for (int e = 0; e < 4; e++) h[e] = __float2half_rn(f[e]);
        *(uint2*)(dh + i) = make_uint2(pack_h(h[0], h[1]), pack_h(h[2], h[3]));
        if (y != 0) {
            __half l[4];
#pragma unroll
            for (int e = 0; e < 4; e++)
                l[e] = __float2half_rn(f[e] - __half2float(h[e]));
            *(uint2*)(dl + i) = make_uint2(pack_h(l[0], l[1]), pack_h(l[2], l[3]));
        }
    }
}

// ---------------------------------------------------------------------------
// fp16 asymmetric-split GEMM: C = A(single) @ (Wh + Wl)^T, 2 mma per tile-k16.
// CTA 128x128, 8 warps (2m x 4n), k-stage 64 (4 k16 steps), cp.async 2-stage,
// 1 sync/stage (16 total), 2 CTA/SM.
// MODE 0: QKV (z selects W; epilogue: Q -> single (x0.125), K/V -> hi+lo)
// MODE 1: O-proj (A = g_AOh; fp32 epilogue to out)
// ---------------------------------------------------------------------------
#define SSTR 72                        // smem row stride in halves (64 data + 8 pad)
#define SSTRB 144
#define STAGE_B   (128 * SSTR * 2)     // 18432 bytes per array per stage
#define GEMM_SMEM (6 * STAGE_B)        // 110592: A(2 stages) + Bh(2) + Bl(2)
#define NST       (D_MODEL / 64)       // 16 k-stages

template<int MODE>
__global__ __launch_bounds__(256, 2) void gemm_mma(float* __restrict__ outp)
{
    extern __shared__ __half ds[];

    int tid = threadIdx.x;
    int wid = tid >> 5, lane = tid & 31;
    int wm = wid & 1, wn = wid >> 1;
    int rowBase = blockIdx.y * 128, colBase = blockIdx.x * 128;

    const __half *Ag, *Bhg, *Blg;
    if (MODE == 0) {
        int z = blockIdx.z;
        Ag = g_xh;
        Bhg = g_Wh + (size_t)z * NW;  Blg = g_Wl + (size_t)z * NW;
    } else {
        Ag = g_AOh;
        Bhg = g_Wh + 3ull * NW;       Blg = g_Wl + 3ull * NW;
    }
    Ag  += (size_t)rowBase * D_MODEL;
    Bhg += (size_t)colBase * D_MODEL;  Blg += (size_t)colBase * D_MODEL;

    uint32_t u0  = smem_to_u32(ds);
    uint32_t uA  = u0;
    uint32_t uBh = u0 + 2 * STAGE_B;
    uint32_t uBl = u0 + 4 * STAGE_B;

    float acc[4][4][4];
#pragma unroll
    for (int i = 0; i < 4; i++)
#pragma unroll
        for (int j = 0; j < 4; j++)
#pragma unroll
            for (int c = 0; c < 4; c++) acc[i][j][c] = 0.f;

    uint32_t aOff = (uint32_t)((wm * 64 + (lane & 15)) * SSTRB + (lane >> 4) * 16);
    uint32_t bOff = (uint32_t)((wn * 32 + (lane & 7) + ((lane >> 4) & 1) * 8) * SSTRB
                               + ((lane >> 3) & 1) * 16);

    auto issue = [&](int st) {
        uint32_t sb = (uint32_t)((st & 1) * STAGE_B);
        int k0 = st * 64;
#pragma unroll
        for (int u = 0; u < 4; u++) {
            int f = tid + 256 * u;
            int row = f >> 3, seg = (f & 7) * 8;
            uint32_t so = sb + (uint32_t)(row * SSTR + seg) * 2;
            size_t g = (size_t)row * D_MODEL + k0 + seg;
            cp16(uA  + so, Ag  + g);
            cp16(uBh + so, Bhg + g);
            cp16(uBl + so, Blg + g);
        }
        CP_COMMIT();
    };

    issue(0);

    for (int st = 0; st < NST; st++) {
        uint32_t sOff = (uint32_t)((st & 1) * STAGE_B);
        CP_WAIT0();
        __syncthreads();               // stage st visible; all warps done with st-1
        if (st < NST - 1) issue(st + 1);

#pragma unroll
        for (int ks = 0; ks < 4; ks++) {
            uint32_t kb = (uint32_t)(ks * 32);
            uint32_t bh[2][4], bl[2][4];
#pragma unroll
            for (int p = 0; p < 2; p++) {
                uint32_t o = sOff + bOff + p * 16 * SSTRB + kb;
                ldsm_x4(bh[p], uBh + o);
                ldsm_x4(bl[p], uBl + o);
            }
#pragma unroll
            for (int mt = 0; mt < 4; mt++) {
                uint32_t ah[4];
                ldsm_x4(ah, uA + sOff + aOff + mt * 16 * SSTRB + kb);
#pragma unroll
                for (int nt = 0; nt < 4; nt++) {
                    int p = nt >> 1, q = (nt & 1) * 2;
                    mma_f16(acc[mt][nt], ah, bh[p][q], bh[p][q + 1]);
                    mma_f16(acc[mt][nt], ah, bl[p][q], bl[p][q + 1]);
                }
            }
        }
    }

    // Epilogue
#pragma unroll
    for (int mt = 0; mt < 4; mt++)
#pragma unroll
        for (int nt = 0; nt < 4; nt++) {
            int row0 = rowBase + wm * 64 + mt * 16 + (lane >> 2);
            int col  = colBase + wn * 32 + nt * 8 + (lane & 3) * 2;
#pragma unroll
            for (int cp = 0; cp < 2; cp++) {
                int row = row0 + cp * 8;
                float v0 = acc[mt][nt][cp * 2], v1 = acc[mt][nt][cp * 2 + 1];
                if (MODE == 1) {
                    *(float2*)(outp + (size_t)row * D_MODEL + col) = make_float2(v0, v1);
                } else {
                    int z = blockIdx.z;
                    if (z == 0) { v0 *= 0.125f; v1 *= 0.125f; }
                    int b = row >> 11, s = row & 2047;
                    int h = col >> 6, d = col & 63;
                    size_t idx = ((size_t)(b * NUM_HEADS + h) * SEQ + s) * DK + d;
                    __half h0 = __float2half_rn(v0), h1 = __float2half_rn(v1);
                    __half* dh = (z == 0) ? g_Qh : (z == 1) ? g_Kh : g_Vh;
                    *(uint32_t*)(dh + idx) = pack_h(h0, h1);
                    if (z != 0) {
                        __half* dl = (z == 1) ? g_Kl : g_Vl;
                        __half l0 = __float2half_rn(v0 - __half2float(h0));
                        __half l1 = __float2half_rn(v1 - __half2float(h1));
                        *(uint32_t*)(dl + idx) = pack_h(l0, l1);
                    }
                }
            }
        }
}

// ---------------------------------------------------------------------------
// Flash attention, fp16 asymmetric split (exact R10 configuration):
//   S = Qh*(Kh+Kl)  (Q single, 2 mma);  O += Ph*(Vh+Vl)  (P single, 2 mma)
// CTA: 128 q rows, 8 warps, K-tile 64, cp.async 2-stage K/V, 1 sync/tile.
// ---------------------------------------------------------------------------
#define FSTR  72                      // smem row stride (halves)
#define FSTRB 144
#define FQ_ELE (128 * FSTR)           // 9216 halves
#define FQB    (FQ_ELE * 2)           // 18432 bytes
#define FK_ELE (64 * FSTR)            // 4608 halves
#define FKB    (FK_ELE * 2)           // 9216 bytes per array per stage
#define FL_SMEM (FQB + 8 * FKB)       // 92160 bytes
#define NKT    (SEQ / 64)             // 32 k-tiles

__global__ __launch_bounds__(256) void flash_mma(const int* __restrict__ am)
{
    extern __shared__ __half sb[];
    __shared__ int msk[2][64];

    int tid = threadIdx.x;
    int wid = tid >> 5, lane = tid & 31;
    int g = lane >> 2, tig = lane & 3;
    int q0 = blockIdx.x * 128;
    int h  = blockIdx.y;
    int b  = blockIdx.z;

    size_t hoff = ((size_t)(b * NUM_HEADS + h) * SEQ) * DK;

    uint32_t uB  = smem_to_u32(sb);
    uint32_t uQ  = uB;
    uint32_t uKh = uB + FQB;
    uint32_t uKl = uKh + 2 * FKB;
    uint32_t uVh = uKh + 4 * FKB;
    uint32_t uVl = uKh + 6 * FKB;
    uint32_t umsk = smem_to_u32(msk);

    const __half* Khg = g_Kh + hoff;
    const __half* Klg = g_Kl + hoff;
    const __half* Vhg = g_Vh + hoff;
    const __half* Vlg = g_Vl + hoff;

    auto issueKV = [&](int kt) {
        uint32_t sbyte = (uint32_t)((kt & 1) * FKB);
        size_t k0d = (size_t)(kt * 64) * DK;
#pragma unroll
        for (int u = 0; u < 2; u++) {
            int f = tid + 256 * u;
            int row = f >> 3, seg = (f & 7) * 8;
            uint32_t so = sbyte + (uint32_t)(row * FSTR + seg) * 2;
            size_t go = k0d + (size_t)row * DK + seg;
            cp16(uKh + so, Khg + go);
            cp16(uKl + so, Klg + go);
            cp16(uVh + so, Vhg + go);
            cp16(uVl + so, Vlg + go);
        }
        if (tid < 64)
            cp4(umsk + (uint32_t)(((kt & 1) * 64 + tid) * 4),
                am + (size_t)b * SEQ + kt * 64 + tid);
        CP_COMMIT();
    };

    issueKV(0);

    // Load Q (single fp16, 128 rows x 64 halves) behind the first K/V fetch.
    const __half* Qg = g_Qh + hoff + (size_t)q0 * DK;
    {
        int row = tid >> 1, seg = (tid & 1) * 32;
        *(uint4*)(sb + row * FSTR + seg)      = *(const uint4*)(Qg + (size_t)row * DK + seg);
        *(uint4*)(sb + row * FSTR + seg + 8)  = *(const uint4*)(Qg + (size_t)row * DK + seg + 8);
        *(uint4*)(sb + row * FSTR + seg + 16) = *(const uint4*)(Qg + (size_t)row * DK + seg + 16);
        *(uint4*)(sb + row * FSTR + seg + 24) = *(const uint4*)(Qg + (size_t)row * DK + seg + 24);
    }
    __syncthreads();

    uint32_t qOff = (uint32_t)((wid * 16 + (lane & 15)) * FSTRB + (lane >> 4) * 16);
    uint32_t qh[4][4];
#pragma unroll
    for (int kst = 0; kst < 4; kst++)
        ldsm_x4(qh[kst], uQ + qOff + kst * 32);

    float oacc[8][4];
#pragma unroll
    for (int nt = 0; nt < 8; nt++)
#pragma unroll
        for (int c = 0; c < 4; c++) oacc[nt][c] = 0.f;
    float mrow[2] = {-1e30f, -1e30f}, lrow[2] = {0.f, 0.f};

    uint32_t bOffK = (uint32_t)(((lane & 7) + ((lane >> 4) & 1) * 8) * FSTRB + ((lane >> 3) & 1) * 16);
    uint32_t vOff  = (uint32_t)((lane & 15) * FSTRB + (lane >> 4) * 16);

    for (int kt = 0; kt < NKT; kt++) {
        int stage = kt & 1;
        CP_WAIT0();
        __syncthreads();          // stage kt visible; all warps done with buffer kt-1
        if (kt < NKT - 1) issueKV(kt + 1);

        uint32_t skh = uKh + stage * FKB, skl = uKl + stage * FKB;
        uint32_t svh = uVh + stage * FKB, svl = uVl + stage * FKB;

        // ----- S = Qh (Kh + Kl)^T -----
        float s[8][4];
#pragma unroll
        for (int nt = 0; nt < 8; nt++)
#pragma unroll
            for (int c = 0; c < 4; c++) s[nt][c] = 0.f;

#pragma unroll
        for (int p = 0; p < 4; p++) {
#pragma unroll
            for (int kst = 0; kst < 4; kst++) {
                uint32_t kh[4], kl[4];
                uint32_t o = p * 16 * FSTRB + kst * 32 + bOffK;
                ldsm_x4(kh, skh + o);
                ldsm_x4(kl, skl + o);
                int nt0 = 2 * p, nt1 = 2 * p + 1;
                mma_f16(s[nt0], qh[kst], kh[0], kh[1]);
                mma_f16(s[nt0], qh[kst], kl[0], kl[1]);
                mma_f16(s[nt1], qh[kst], kh[2], kh[3]);
                mma_f16(s[nt1], qh[kst], kl[2], kl[3]);
            }
        }

        // ----- mask -----
#pragma unroll
        for (int nt = 0; nt < 8; nt++) {
            int c0 = nt * 8 + tig * 2;
            if (msk[stage][c0] == 0)     { s[nt][0] = -1e30f; s[nt][2] = -1e30f; }
            if (msk[stage][c0 + 1] == 0) { s[nt][1] = -1e30f; s[nt][3] = -1e30f; }
        }

        // ----- online softmax (rows g and g+8) -----
        float mx0 = -1e30f, mx1 = -1e30f;
#pragma unroll
        for (int nt = 0; nt < 8; nt++) {
            mx0 = fmaxf(mx0, fmaxf(s[nt][0], s[nt][1]));
            mx1 = fmaxf(mx1, fmaxf(s[nt][2], s[nt][3]));
        }
#pragma unroll
        for (int o = 1; o <= 2; o <<= 1) {
            mx0 = fmaxf(mx0, __shfl_xor_sync(0xffffffffu, mx0, o));
            mx1 = fmaxf(mx1, __shfl_xor_sync(0xffffffffu, mx1, o));
        }
        float mn0 = fmaxf(mrow[0], mx0), mn1 = fmaxf(mrow[1], mx1);
        float al0 = __expf(mrow[0] - mn0), al1 = __expf(mrow[1] - mn1);
        float rs0 = 0.f, rs1 = 0.f;
#pragma unroll
        for (int nt = 0; nt < 8; nt++) {
            s[nt][0] = __expf(s[nt][0] - mn0); rs0 += s[nt][0];
            s[nt][1] = __expf(s[nt][1] - mn0); rs0 += s[nt][1];
            s[nt][2] = __expf(s[nt][2] - mn1); rs1 += s[nt][2];
            s[nt][3] = __expf(s[nt][3] - mn1); rs1 += s[nt][3];
        }
#pragma unroll
        for (int o = 1; o <= 2; o <<= 1) {
            rs0 += __shfl_xor_sync(0xffffffffu, rs0, o);
            rs1 += __shfl_xor_sync(0xffffffffu, rs1, o);
        }
        lrow[0] = lrow[0] * al0 + rs0;  mrow[0] = mn0;
        lrow[1] = lrow[1] * al1 + rs1;  mrow[1] = mn1;
#pragma unroll
        for (int nt = 0; nt < 8; nt++) {
            oacc[nt][0] *= al0; oacc[nt][1] *= al0;
            oacc[nt][2] *= al1; oacc[nt][3] *= al1;
        }

        // ----- P -> single-fp16 A-fragments -----
        uint32_t pa[4][4];
#pragma unroll
        for (int kc = 0; kc < 4; kc++) {
            const float* t0 = s[2 * kc];
            const float* t1 = s[2 * kc + 1];
            pa[kc][0] = pack_h(__float2half_rn(t0[0]), __float2half_rn(t0[1]));
            pa[kc][1] = pack_h(__float2half_rn(t0[2]), __float2half_rn(t0[3]));
            pa[kc][2] = pack_h(__float2half_rn(t1[0]), __float2half_rn(t1[1]));
            pa[kc][3] = pack_h(__float2half_rn(t1[2]), __float2half_rn(t1[3]));
        }

        // ----- O += P (Vh + Vl) -----
#pragma unroll
        for (int kc = 0; kc < 4; kc++) {
            uint32_t vh[4][4], vl[4][4];
#pragma unroll
            for (int p = 0; p < 4; p++) {
                uint32_t o = kc * 16 * FSTRB + p * 32 + vOff;
                ldsm_x4_t(vh[p], svh + o);
                ldsm_x4_t(vl[p], svl + o);
            }
#pragma unroll
            for (int nt = 0; nt < 8; nt++) {
                int p = nt >> 1, q = (nt & 1) * 2;
                mma_f16(oacc[nt], pa[kc], vh[p][q], vh[p][q + 1]);
                mma_f16(oacc[nt], pa[kc], vl[p][q], vl[p][q + 1]);
            }
        }
    }

    // ----- epilogue: normalize, single-fp16 write to g_AOh -----
    float inv0 = (lrow[0] > 0.f) ? (1.f / lrow[0]) : 0.f;
    float inv1 = (lrow[1] > 0.f) ? (1.f / lrow[1]) : 0.f;
    int r0 = q0 + wid * 16 + g;
    int r1 = r0 + 8;
#pragma unroll
    for (int nt = 0; nt < 8; nt++) {
        int d0 = nt * 8 + tig * 2;
        size_t i0 = ((size_t)b * SEQ + r0) * D_MODEL + h * DK + d0;
        size_t i1 = ((size_t)b * SEQ + r1) * D_MODEL + h * DK + d0;
        *(uint32_t*)(g_AOh + i0) = pack_h(__float2half_rn(oacc[nt][0] * inv0),
                                          __float2half_rn(oacc[nt][1] * inv0));
        *(uint32_t*)(g_AOh + i1) = pack_h(__float2half_rn(oacc[nt][2] * inv1),
                                          __float2half_rn(oacc[nt][3] * inv1));
    }
}

// ---------------------------------------------------------------------------
// Launch
// ---------------------------------------------------------------------------
extern "C" void kernel_launch(void* const* d_in, const int* in_sizes, int n_in,
                              void* d_out, int out_size)
{
    const float* x  = (const float*)d_in[0];
    const int*   am = (const int*)d_in[1];
    const float* Wq = (const float*)d_in[2];
    const float* Wk = (const float*)d_in[3];
    const float* Wv = (const float*)d_in[4];
    const float* Wo = (const float*)d_in[5];
    float* out = (float*)d_out;

    cudaFuncSetAttribute(gemm_mma<0>, cudaFuncAttributeMaxDynamicSharedMemorySize, GEMM_SMEM);
    cudaFuncSetAttribute(gemm_mma<1>, cudaFuncAttributeMaxDynamicSharedMemorySize, GEMM_SMEM);
    cudaFuncSetAttribute(flash_mma, cudaFuncAttributeMaxDynamicSharedMemorySize, FL_SMEM);

    dim3 gc(1024, 5);
    cvt_all<<<gc, 256>>>(x, Wq, Wk, Wv, Wo);

    dim3 gq(D_MODEL / 128, NROWS / 128, 3);     // (8, 32, 3)
    gemm_mma<0><<<gq, 256, GEMM_SMEM>>>(nullptr);

    dim3 ga(SEQ / 128, NUM_HEADS, BATCH);       // (16, 16, 2)
    flash_mma<<<ga, 256, FL_SMEM>>>(am);

    dim3 go(D_MODEL / 128, NROWS / 128, 1);     // (8, 32)
    gemm_mma<1><<<go, 256, GEMM_SMEM>>>(out);
}

// round 14
// speedup vs baseline: 1.1275x; 1.0721x over previous
#include <cuda_runtime.h>
#include <cuda_fp16.h>
#include <cstdint>
#include <math.h>

// Problem constants
#define D_MODEL   1024
#define NUM_HEADS 16
#define DK        64
#define BATCH     2
#define SEQ       2048
#define NROWS     (BATCH * SEQ)      // 4096
#define NX        (NROWS * D_MODEL)  // 4194304
#define NW        (D_MODEL * D_MODEL)// 1048576

// ---------------------------------------------------------------------------
// Scratch (device globals: allocation-free rule)
// fp16 asymmetric split: "A" operands stored single, "B" operands hi+lo.
// ---------------------------------------------------------------------------
__device__ __half g_xh[NX];                        // x single fp16
__device__ __half g_Wh[4 * NW], g_Wl[4 * NW];      // Wq,Wk,Wv,Wo hi/lo
__device__ __half g_Qh[NX];                        // [b][h][s][d], pre-scaled 0.125
__device__ __half g_Kh[NX], g_Kl[NX];
__device__ __half g_Vh[NX], g_Vl[NX];
__device__ __half g_AOh[NX];                       // attn out single [b][s][h*64+d]

// ---------------------------------------------------------------------------
// PTX helpers (plain sm_100-safe: ldmatrix, mma.sync f16, cp.async)
// ---------------------------------------------------------------------------
__device__ __forceinline__ uint32_t smem_to_u32(const void* p) {
    uint32_t a;
    asm("{ .reg .u64 t; cvta.to.shared.u64 t, %1; cvt.u32.u64 %0, t; }" : "=r"(a) : "l"(p));
    return a;
}
__device__ __forceinline__ void ldsm_x4(uint32_t* r, uint32_t addr) {
    asm volatile("ldmatrix.sync.aligned.m8n8.x4.shared.b16 {%0,%1,%2,%3}, [%4];"
        : "=r"(r[0]), "=r"(r[1]), "=r"(r[2]), "=r"(r[3]) : "r"(addr));
}
__device__ __forceinline__ void ldsm_x4_t(uint32_t* r, uint32_t addr) {
    asm volatile("ldmatrix.sync.aligned.m8n8.x4.trans.shared.b16 {%0,%1,%2,%3}, [%4];"
        : "=r"(r[0]), "=r"(r[1]), "=r"(r[2]), "=r"(r[3]) : "r"(addr));
}
__device__ __forceinline__ void mma_f16(float* d, const uint32_t* a, uint32_t b0, uint32_t b1) {
    asm volatile("mma.sync.aligned.m16n8k16.row.col.f32.f16.f16.f32 "
        "{%0,%1,%2,%3}, {%4,%5,%6,%7}, {%8,%9}, {%0,%1,%2,%3};"
        : "+f"(d[0]), "+f"(d[1]), "+f"(d[2]), "+f"(d[3])
        : "r"(a[0]), "r"(a[1]), "r"(a[2]), "r"(a[3]), "r"(b0), "r"(b1));
}
__device__ __forceinline__ void cp16(uint32_t dst, const void* src) {
    asm volatile("cp.async.cg.shared.global [%0], [%1], 16;" :: "r"(dst), "l"(src));
}
__device__ __forceinline__ void cp4(uint32_t dst, const void* src) {
    asm volatile("cp.async.ca.shared.global [%0], [%1], 4;" :: "r"(dst), "l"(src));
}
#define CP_COMMIT() asm volatile("cp.async.commit_group;" ::: "memory")
#define CP_WAIT0()  asm volatile("cp.async.wait_group 0;" ::: "memory")

__device__ __forceinline__ uint32_t pack_h(__half a, __half b) {
    __half2 t = __halves2half2(a, b);
    return *(uint32_t*)&t;
}

// ---------------------------------------------------------------------------
// Pre-pass: convert x (single fp16) + 4 weights (fp16 hi/lo)
// ---------------------------------------------------------------------------
__global__ __launch_bounds__(256) void cvt_all(
    const float* __restrict__ x,  const float* __restrict__ wq,
    const float* __restrict__ wk, const float* __restrict__ wv,
    const float* __restrict__ wo)
{
    int y = blockIdx.y;
    const float* s = (y == 0) ? x : (y == 1) ? wq : (y == 2) ? wk : (y == 3) ? wv : wo;
    __half* dh = (y == 0) ? g_xh : g_Wh + (size_t)(y - 1) * NW;
    __half* dl = (y == 0) ? (__half*)nullptr : g_Wl + (size_t)(y - 1) * NW;
    size_t n = (y == 0) ? (size_t)NX : (size_t)NW;
    size_t stride = (size_t)gridDim.x * 256 * 4;
    for (size_t i = ((size_t)blockIdx.x * 256 + threadIdx.x) * 4; i < n; i += stride) {
        float4 v = *(const float4*)(s + i);
        float f[4] = {v.x, v.y, v.z, v.w};
        __half h[4];
#pragma unroll
        for (int e = 0; e < 4; e++) h[e] = __float2half_rn(f[e]);
        *(uint2*)(dh + i) = make_uint2(pack_h(h[0], h[1]), pack_h(h[2], h[3]));
        if (y != 0) {
            __half l[4];
#pragma unroll
            for (int e = 0; e < 4; e++)
                l[e] = __float2half_rn(f[e] - __half2float(h[e]));
            *(uint2*)(dl + i) = make_uint2(pack_h(l[0], l[1]), pack_h(l[2], l[3]));
        }
    }
}

// ---------------------------------------------------------------------------
// fp16 asymmetric-split GEMM: C = A(single) @ (Wh + Wl)^T, 2 mma per tile-k16.
// CTA 128x128, 8 warps (2m x 4n), k-stage 64 (4 k16 steps), cp.async 2-stage,
// 1 sync/stage (16 total), 2 CTA/SM.  (unchanged from R13)
// ---------------------------------------------------------------------------
#define SSTR 72                        // smem row stride in halves (64 data + 8 pad)
#define SSTRB 144
#define STAGE_B   (128 * SSTR * 2)     // 18432 bytes per array per stage
#define GEMM_SMEM (6 * STAGE_B)        // 110592: A(2 stages) + Bh(2) + Bl(2)
#define NST       (D_MODEL / 64)       // 16 k-stages

template<int MODE>
__global__ __launch_bounds__(256, 2) void gemm_mma(float* __restrict__ outp)
{
    extern __shared__ __half ds[];

    int tid = threadIdx.x;
    int wid = tid >> 5, lane = tid & 31;
    int wm = wid & 1, wn = wid >> 1;
    int rowBase = blockIdx.y * 128, colBase = blockIdx.x * 128;

    const __half *Ag, *Bhg, *Blg;
    if (MODE == 0) {
        int z = blockIdx.z;
        Ag = g_xh;
        Bhg = g_Wh + (size_t)z * NW;  Blg = g_Wl + (size_t)z * NW;
    } else {
        Ag = g_AOh;
        Bhg = g_Wh + 3ull * NW;       Blg = g_Wl + 3ull * NW;
    }
    Ag  += (size_t)rowBase * D_MODEL;
    Bhg += (size_t)colBase * D_MODEL;  Blg += (size_t)colBase * D_MODEL;

    uint32_t u0  = smem_to_u32(ds);
    uint32_t uA  = u0;
    uint32_t uBh = u0 + 2 * STAGE_B;
    uint32_t uBl = u0 + 4 * STAGE_B;

    float acc[4][4][4];
#pragma unroll
    for (int i = 0; i < 4; i++)
#pragma unroll
        for (int j = 0; j < 4; j++)
#pragma unroll
            for (int c = 0; c < 4; c++) acc[i][j][c] = 0.f;

    uint32_t aOff = (uint32_t)((wm * 64 + (lane & 15)) * SSTRB + (lane >> 4) * 16);
    uint32_t bOff = (uint32_t)((wn * 32 + (lane & 7) + ((lane >> 4) & 1) * 8) * SSTRB
                               + ((lane >> 3) & 1) * 16);

    auto issue = [&](int st) {
        uint32_t sb = (uint32_t)((st & 1) * STAGE_B);
        int k0 = st * 64;
#pragma unroll
        for (int u = 0; u < 4; u++) {
            int f = tid + 256 * u;
            int row = f >> 3, seg = (f & 7) * 8;
            uint32_t so = sb + (uint32_t)(row * SSTR + seg) * 2;
            size_t g = (size_t)row * D_MODEL + k0 + seg;
            cp16(uA  + so, Ag  + g);
            cp16(uBh + so, Bhg + g);
            cp16(uBl + so, Blg + g);
        }
        CP_COMMIT();
    };

    issue(0);

    for (int st = 0; st < NST; st++) {
        uint32_t sOff = (uint32_t)((st & 1) * STAGE_B);
        CP_WAIT0();
        __syncthreads();               // stage st visible; all warps done with st-1
        if (st < NST - 1) issue(st + 1);

#pragma unroll
        for (int ks = 0; ks < 4; ks++) {
            uint32_t kb = (uint32_t)(ks * 32);
            uint32_t bh[2][4], bl[2][4];
#pragma unroll
            for (int p = 0; p < 2; p++) {
                uint32_t o = sOff + bOff + p * 16 * SSTRB + kb;
                ldsm_x4(bh[p], uBh + o);
                ldsm_x4(bl[p], uBl + o);
            }
#pragma unroll
            for (int mt = 0; mt < 4; mt++) {
                uint32_t ah[4];
                ldsm_x4(ah, uA + sOff + aOff + mt * 16 * SSTRB + kb);
#pragma unroll
                for (int nt = 0; nt < 4; nt++) {
                    int p = nt >> 1, q = (nt & 1) * 2;
                    mma_f16(acc[mt][nt], ah, bh[p][q], bh[p][q + 1]);
                    mma_f16(acc[mt][nt], ah, bl[p][q], bl[p][q + 1]);
                }
            }
        }
    }

    // Epilogue
#pragma unroll
    for (int mt = 0; mt < 4; mt++)
#pragma unroll
        for (int nt = 0; nt < 4; nt++) {
            int row0 = rowBase + wm * 64 + mt * 16 + (lane >> 2);
            int col  = colBase + wn * 32 + nt * 8 + (lane & 3) * 2;
#pragma unroll
            for (int cp = 0; cp < 2; cp++) {
                int row = row0 + cp * 8;
                float v0 = acc[mt][nt][cp * 2], v1 = acc[mt][nt][cp * 2 + 1];
                if (MODE == 1) {
                    *(float2*)(outp + (size_t)row * D_MODEL + col) = make_float2(v0, v1);
                } else {
                    int z = blockIdx.z;
                    if (z == 0) { v0 *= 0.125f; v1 *= 0.125f; }
                    int b = row >> 11, s = row & 2047;
                    int h = col >> 6, d = col & 63;
                    size_t idx = ((size_t)(b * NUM_HEADS + h) * SEQ + s) * DK + d;
                    __half h0 = __float2half_rn(v0), h1 = __float2half_rn(v1);
                    __half* dh = (z == 0) ? g_Qh : (z == 1) ? g_Kh : g_Vh;
                    *(uint32_t*)(dh + idx) = pack_h(h0, h1);
                    if (z != 0) {
                        __half* dl = (z == 1) ? g_Kl : g_Vl;
                        __half l0 = __float2half_rn(v0 - __half2float(h0));
                        __half l1 = __float2half_rn(v1 - __half2float(h1));
                        *(uint32_t*)(dl + idx) = pack_h(l0, l1);
                    }
                }
            }
        }
}

// ---------------------------------------------------------------------------
// Flash attention, fp16 asymmetric split — R13 body, NOW 2 CTA/SM
// (__launch_bounds__(256, 2): regs capped 128, smem 92160*2 = 184 KB <= 228).
// ---------------------------------------------------------------------------
#define FSTR  72                      // smem row stride (halves)
#define FSTRB 144
#define FQ_ELE (128 * FSTR)           // 9216 halves
#define FQB    (FQ_ELE * 2)           // 18432 bytes
#define FK_ELE (64 * FSTR)            // 4608 halves
#define FKB    (FK_ELE * 2)           // 9216 bytes per array per stage
#define FL_SMEM (FQB + 8 * FKB)       // 92160 bytes
#define NKT    (SEQ / 64)             // 32 k-tiles

__global__ __launch_bounds__(256, 2) void flash_mma(const int* __restrict__ am)
{
    extern __shared__ __half sb[];
    __shared__ int msk[2][64];

    int tid = threadIdx.x;
    int wid = tid >> 5, lane = tid & 31;
    int g = lane >> 2, tig = lane & 3;
    int q0 = blockIdx.x * 128;
    int h  = blockIdx.y;
    int b  = blockIdx.z;

    size_t hoff = ((size_t)(b * NUM_HEADS + h) * SEQ) * DK;

    uint32_t uB  = smem_to_u32(sb);
    uint32_t uQ  = uB;
    uint32_t uKh = uB + FQB;
    uint32_t uKl = uKh + 2 * FKB;
    uint32_t uVh = uKh + 4 * FKB;
    uint32_t uVl = uKh + 6 * FKB;
    uint32_t umsk = smem_to_u32(msk);

    const __half* Khg = g_Kh + hoff;
    const __half* Klg = g_Kl + hoff;
    const __half* Vhg = g_Vh + hoff;
    const __half* Vlg = g_Vl + hoff;

    auto issueKV = [&](int kt) {
        uint32_t sbyte = (uint32_t)((kt & 1) * FKB);
        size_t k0d = (size_t)(kt * 64) * DK;
#pragma unroll
        for (int u = 0; u < 2; u++) {
            int f = tid + 256 * u;
            int row = f >> 3, seg = (f & 7) * 8;
            uint32_t so = sbyte + (uint32_t)(row * FSTR + seg) * 2;
            size_t go = k0d + (size_t)row * DK + seg;
            cp16(uKh + so, Khg + go);
            cp16(uKl + so, Klg + go);
            cp16(uVh + so, Vhg + go);
            cp16(uVl + so, Vlg + go);
        }
        if (tid < 64)
            cp4(umsk + (uint32_t)(((kt & 1) * 64 + tid) * 4),
                am + (size_t)b * SEQ + kt * 64 + tid);
        CP_COMMIT();
    };

    issueKV(0);

    // Load Q (single fp16, 128 rows x 64 halves) behind the first K/V fetch.
    const __half* Qg = g_Qh + hoff + (size_t)q0 * DK;
    {
        int row = tid >> 1, seg = (tid & 1) * 32;
        *(uint4*)(sb + row * FSTR + seg)      = *(const uint4*)(Qg + (size_t)row * DK + seg);
        *(uint4*)(sb + row * FSTR + seg + 8)  = *(const uint4*)(Qg + (size_t)row * DK + seg + 8);
        *(uint4*)(sb + row * FSTR + seg + 16) = *(const uint4*)(Qg + (size_t)row * DK + seg + 16);
        *(uint4*)(sb + row * FSTR + seg + 24) = *(const uint4*)(Qg + (size_t)row * DK + seg + 24);
    }
    __syncthreads();

    uint32_t qOff = (uint32_t)((wid * 16 + (lane & 15)) * FSTRB + (lane >> 4) * 16);
    uint32_t qh[4][4];
#pragma unroll
    for (int kst = 0; kst < 4; kst++)
        ldsm_x4(qh[kst], uQ + qOff + kst * 32);

    float oacc[8][4];
#pragma unroll
    for (int nt = 0; nt < 8; nt++)
#pragma unroll
        for (int c = 0; c < 4; c++) oacc[nt][c] = 0.f;
    float mrow[2] = {-1e30f, -1e30f}, lrow[2] = {0.f, 0.f};

    uint32_t bOffK = (uint32_t)(((lane & 7) + ((lane >> 4) & 1) * 8) * FSTRB + ((lane >> 3) & 1) * 16);
    uint32_t vOff  = (uint32_t)((lane & 15) * FSTRB + (lane >> 4) * 16);

    for (int kt = 0; kt < NKT; kt++) {
        int stage = kt & 1;
        CP_WAIT0();
        __syncthreads();          // stage kt visible; all warps done with buffer kt-1
        if (kt < NKT - 1) issueKV(kt + 1);

        uint32_t skh = uKh + stage * FKB, skl = uKl + stage * FKB;
        uint32_t svh = uVh + stage * FKB, svl = uVl + stage * FKB;

        // ----- S = Qh (Kh + Kl)^T -----
        float s[8][4];
#pragma unroll
        for (int nt = 0; nt < 8; nt++)
#pragma unroll
            for (int c = 0; c < 4; c++) s[nt][c] = 0.f;

#pragma unroll
        for (int p = 0; p < 4; p++) {
#pragma unroll
            for (int kst = 0; kst < 4; kst++) {
                uint32_t kh[4], kl[4];
                uint32_t o = p * 16 * FSTRB + kst * 32 + bOffK;
                ldsm_x4(kh, skh + o);
                ldsm_x4(kl, skl + o);
                int nt0 = 2 * p, nt1 = 2 * p + 1;
                mma_f16(s[nt0], qh[kst], kh[0], kh[1]);
                mma_f16(s[nt0], qh[kst], kl[0], kl[1]);
                mma_f16(s[nt1], qh[kst], kh[2], kh[3]);
                mma_f16(s[nt1], qh[kst], kl[2], kl[3]);
            }
        }

        // ----- mask -----
#pragma unroll
        for (int nt = 0; nt < 8; nt++) {
            int c0 = nt * 8 + tig * 2;
            if (msk[stage][c0] == 0)     { s[nt][0] = -1e30f; s[nt][2] = -1e30f; }
            if (msk[stage][c0 + 1] == 0) { s[nt][1] = -1e30f; s[nt][3] = -1e30f; }
        }

        // ----- online softmax (rows g and g+8) -----
        float mx0 = -1e30f, mx1 = -1e30f;
#pragma unroll
        for (int nt = 0; nt < 8; nt++) {
            mx0 = fmaxf(mx0, fmaxf(s[nt][0], s[nt][1]));
            mx1 = fmaxf(mx1, fmaxf(s[nt][2], s[nt][3]));
        }
#pragma unroll
        for (int o = 1; o <= 2; o <<= 1) {
            mx0 = fmaxf(mx0, __shfl_xor_sync(0xffffffffu, mx0, o));
            mx1 = fmaxf(mx1, __shfl_xor_sync(0xffffffffu, mx1, o));
        }
        float mn0 = fmaxf(mrow[0], mx0), mn1 = fmaxf(mrow[1], mx1);
        float al0 = __expf(mrow[0] - mn0), al1 = __expf(mrow[1] - mn1);
        float rs0 = 0.f, rs1 = 0.f;
#pragma unroll
        for (int nt = 0; nt < 8; nt++) {
            s[nt][0] = __expf(s[nt][0] - mn0); rs0 += s[nt][0];
            s[nt][1] = __expf(s[nt][1] - mn0); rs0 += s[nt][1];
            s[nt][2] = __expf(s[nt][2] - mn1); rs1 += s[nt][2];
            s[nt][3] = __expf(s[nt][3] - mn1); rs1 += s[nt][3];
        }
#pragma unroll
        for (int o = 1; o <= 2; o <<= 1) {
            rs0 += __shfl_xor_sync(0xffffffffu, rs0, o);
            rs1 += __shfl_xor_sync(0xffffffffu, rs1, o);
        }
        lrow[0] = lrow[0] * al0 + rs0;  mrow[0] = mn0;
        lrow[1] = lrow[1] * al1 + rs1;  mrow[1] = mn1;
#pragma unroll
        for (int nt = 0; nt < 8; nt++) {
            oacc[nt][0] *= al0; oacc[nt][1] *= al0;
            oacc[nt][2] *= al1; oacc[nt][3] *= al1;
        }

        // ----- P -> single-fp16 A-fragments -----
        uint32_t pa[4][4];
#pragma unroll
        for (int kc = 0; kc < 4; kc++) {
            const float* t0 = s[2 * kc];
            const float* t1 = s[2 * kc + 1];
            pa[kc][0] = pack_h(__float2half_rn(t0[0]), __float2half_rn(t0[1]));
            pa[kc][1] = pack_h(__float2half_rn(t0[2]), __float2half_rn(t0[3]));
            pa[kc][2] = pack_h(__float2half_rn(t1[0]), __float2half_rn(t1[1]));
            pa[kc][3] = pack_h(__float2half_rn(t1[2]), __float2half_rn(t1[3]));
        }

        // ----- O += P (Vh + Vl) -----
#pragma unroll
        for (int kc = 0; kc < 4; kc++) {
            uint32_t vh[4][4], vl[4][4];
#pragma unroll
            for (int p = 0; p < 4; p++) {
                uint32_t o = kc * 16 * FSTRB + p * 32 + vOff;
                ldsm_x4_t(vh[p], svh + o);
                ldsm_x4_t(vl[p], svl + o);
            }
#pragma unroll
            for (int nt = 0; nt < 8; nt++) {
                int p = nt >> 1, q = (nt & 1) * 2;
                mma_f16(oacc[nt], pa[kc], vh[p][q], vh[p][q + 1]);
                mma_f16(oacc[nt], pa[kc], vl[p][q], vl[p][q + 1]);
            }
        }
    }

    // ----- epilogue: normalize, single-fp16 write to g_AOh -----
    float inv0 = (lrow[0] > 0.f) ? (1.f / lrow[0]) : 0.f;
    float inv1 = (lrow[1] > 0.f) ? (1.f / lrow[1]) : 0.f;
    int r0 = q0 + wid * 16 + g;
    int r1 = r0 + 8;
#pragma unroll
    for (int nt = 0; nt < 8; nt++) {
        int d0 = nt * 8 + tig * 2;
        size_t i0 = ((size_t)b * SEQ + r0) * D_MODEL + h * DK + d0;
        size_t i1 = ((size_t)b * SEQ + r1) * D_MODEL + h * DK + d0;
        *(uint32_t*)(g_AOh + i0) = pack_h(__float2half_rn(oacc[nt][0] * inv0),
                                          __float2half_rn(oacc[nt][1] * inv0));
        *(uint32_t*)(g_AOh + i1) = pack_h(__float2half_rn(oacc[nt][2] * inv1),
                                          __float2half_rn(oacc[nt][3] * inv1));
    }
}

// ---------------------------------------------------------------------------
// Launch
// ---------------------------------------------------------------------------
extern "C" void kernel_launch(void* const* d_in, const int* in_sizes, int n_in,
                              void* d_out, int out_size)
{
    const float* x  = (const float*)d_in[0];
    const int*   am = (const int*)d_in[1];
    const float* Wq = (const float*)d_in[2];
    const float* Wk = (const float*)d_in[3];
    const float* Wv = (const float*)d_in[4];
    const float* Wo = (const float*)d_in[5];
    float* out = (float*)d_out;

    cudaFuncSetAttribute(gemm_mma<0>, cudaFuncAttributeMaxDynamicSharedMemorySize, GEMM_SMEM);
    cudaFuncSetAttribute(gemm_mma<1>, cudaFuncAttributeMaxDynamicSharedMemorySize, GEMM_SMEM);
    cudaFuncSetAttribute(flash_mma, cudaFuncAttributeMaxDynamicSharedMemorySize, FL_SMEM);

    dim3 gc(1024, 5);
    cvt_all<<<gc, 256>>>(x, Wq, Wk, Wv, Wo);

    dim3 gq(D_MODEL / 128, NROWS / 128, 3);     // (8, 32, 3)
    gemm_mma<0><<<gq, 256, GEMM_SMEM>>>(nullptr);

    dim3 ga(SEQ / 128, NUM_HEADS, BATCH);       // (16, 16, 2)
    flash_mma<<<ga, 256, FL_SMEM>>>(am);

    dim3 go(D_MODEL / 128, NROWS / 128, 1);     // (8, 32)
    gemm_mma<1><<<go, 256, GEMM_SMEM>>>(out);
}

// round 15
// speedup vs baseline: 1.2407x; 1.1004x over previous
#include <cuda_runtime.h>
#include <cuda_fp16.h>
#include <cstdint>
#include <math.h>

// Problem constants
#define D_MODEL   1024
#define NUM_HEADS 16
#define DK        64
#define BATCH     2
#define SEQ       2048
#define NROWS     (BATCH * SEQ)      // 4096
#define NX        (NROWS * D_MODEL)  // 4194304
#define NW        (D_MODEL * D_MODEL)// 1048576

// ---------------------------------------------------------------------------
// Scratch (device globals: allocation-free rule)
// fp16 asymmetric split: weights + K hi+lo; x, Q, V, AO single fp16.
// ---------------------------------------------------------------------------
__device__ __half g_xh[NX];                        // x single fp16
__device__ __half g_Wh[4 * NW], g_Wl[4 * NW];      // Wq,Wk,Wv,Wo hi/lo
__device__ __half g_Qh[NX];                        // [b][h][s][d], pre-scaled 0.125
__device__ __half g_Kh[NX], g_Kl[NX];
__device__ __half g_Vh[NX];                        // V single fp16
__device__ __half g_AOh[NX];                       // attn out single [b][s][h*64+d]

// ---------------------------------------------------------------------------
// PTX helpers (plain sm_100-safe: ldmatrix, mma.sync f16, cp.async)
// ---------------------------------------------------------------------------
__device__ __forceinline__ uint32_t smem_to_u32(const void* p) {
    uint32_t a;
    asm("{ .reg .u64 t; cvta.to.shared.u64 t, %1; cvt.u32.u64 %0, t; }" : "=r"(a) : "l"(p));
    return a;
}
__device__ __forceinline__ void ldsm_x4(uint32_t* r, uint32_t addr) {
    asm volatile("ldmatrix.sync.aligned.m8n8.x4.shared.b16 {%0,%1,%2,%3}, [%4];"
        : "=r"(r[0]), "=r"(r[1]), "=r"(r[2]), "=r"(r[3]) : "r"(addr));
}
__device__ __forceinline__ void ldsm_x4_t(uint32_t* r, uint32_t addr) {
    asm volatile("ldmatrix.sync.aligned.m8n8.x4.trans.shared.b16 {%0,%1,%2,%3}, [%4];"
        : "=r"(r[0]), "=r"(r[1]), "=r"(r[2]), "=r"(r[3]) : "r"(addr));
}
__device__ __forceinline__ void mma_f16(float* d, const uint32_t* a, uint32_t b0, uint32_t b1) {
    asm volatile("mma.sync.aligned.m16n8k16.row.col.f32.f16.f16.f32 "
        "{%0,%1,%2,%3}, {%4,%5,%6,%7}, {%8,%9}, {%0,%1,%2,%3};"
        : "+f"(d[0]), "+f"(d[1]), "+f"(d[2]), "+f"(d[3])
        : "r"(a[0]), "r"(a[1]), "r"(a[2]), "r"(a[3]), "r"(b0), "r"(b1));
}
__device__ __forceinline__ void cp16(uint32_t dst, const void* src) {
    asm volatile("cp.async.cg.shared.global [%0], [%1], 16;" :: "r"(dst), "l"(src));
}
__device__ __forceinline__ void cp4(uint32_t dst, const void* src) {
    asm volatile("cp.async.ca.shared.global [%0], [%1], 4;" :: "r"(dst), "l"(src));
}
#define CP_COMMIT() asm volatile("cp.async.commit_group;" ::: "memory")
#define CP_WAIT0()  asm volatile("cp.async.wait_group 0;" ::: "memory")

__device__ __forceinline__ uint32_t pack_h(__half a, __half b) {
    __half2 t = __halves2half2(a, b);
    return *(uint32_t*)&t;
}

// ---------------------------------------------------------------------------
// Pre-pass: convert x (single fp16) + 4 weights (fp16 hi/lo)
// ---------------------------------------------------------------------------
__global__ __launch_bounds__(256) void cvt_all(
    const float* __restrict__ x,  const float* __restrict__ wq,
    const float* __restrict__ wk, const float* __restrict__ wv,
    const float* __restrict__ wo)
{
    int y = blockIdx.y;
    const float* s = (y == 0) ? x : (y == 1) ? wq : (y == 2) ? wk : (y == 3) ? wv : wo;
    __half* dh = (y == 0) ? g_xh : g_Wh + (size_t)(y - 1) * NW;
    __half* dl = (y == 0) ? (__half*)nullptr : g_Wl + (size_t)(y - 1) * NW;
    size_t n = (y == 0) ? (size_t)NX : (size_t)NW;
    size_t stride = (size_t)gridDim.x * 256 * 4;
    for (size_t i = ((size_t)blockIdx.x * 256 + threadIdx.x) * 4; i < n; i += stride) {
        float4 v = *(const float4*)(s + i);
        float f[4] = {v.x, v.y, v.z, v.w};
        __half h[4];
#pragma unroll
        for (int e = 0; e < 4; e++) h[e] = __float2half_rn(f[e]);
        *(uint2*)(dh + i) = make_uint2(pack_h(h[0], h[1]), pack_h(h[2], h[3]));
        if (y != 0) {
            __half l[4];
#pragma unroll
            for (int e = 0; e < 4; e++)
                l[e] = __float2half_rn(f[e] - __half2float(h[e]));
            *(uint2*)(dl + i) = make_uint2(pack_h(l[0], l[1]), pack_h(l[2], l[3]));
        }
    }
}

// ---------------------------------------------------------------------------
// fp16 asymmetric-split GEMM: C = A(single) @ (Wh + Wl)^T, 2 mma per tile-k16.
// CTA 128x128, 8 warps (2m x 4n), k-stage 64 (4 k16 steps), cp.async 2-stage,
// 1 sync/stage (16 total), 2 CTA/SM.
// MODE 0: QKV (z selects W; epilogue: Q x0.125 single, K hi+lo, V single)
// MODE 1: O-proj (A = g_AOh; fp32 epilogue to out)
// ---------------------------------------------------------------------------
#define SSTR 72                        // smem row stride in halves (64 data + 8 pad)
#define SSTRB 144
#define STAGE_B   (128 * SSTR * 2)     // 18432 bytes per array per stage
#define GEMM_SMEM (6 * STAGE_B)        // 110592: A(2 stages) + Bh(2) + Bl(2)
#define NST       (D_MODEL / 64)       // 16 k-stages

template<int MODE>
__global__ __launch_bounds__(256, 2) void gemm_mma(float* __restrict__ outp)
{
    extern __shared__ __half ds[];

    int tid = threadIdx.x;
    int wid = tid >> 5, lane = tid & 31;
    int wm = wid & 1, wn = wid >> 1;
    int rowBase = blockIdx.y * 128, colBase = blockIdx.x * 128;

    const __half *Ag, *Bhg, *Blg;
    if (MODE == 0) {
        int z = blockIdx.z;
        Ag = g_xh;
        Bhg = g_Wh + (size_t)z * NW;  Blg = g_Wl + (size_t)z * NW;
    } else {
        Ag = g_AOh;
        Bhg = g_Wh + 3ull * NW;       Blg = g_Wl + 3ull * NW;
    }
    Ag  += (size_t)rowBase * D_MODEL;
    Bhg += (size_t)colBase * D_MODEL;  Blg += (size_t)colBase * D_MODEL;

    uint32_t u0  = smem_to_u32(ds);
    uint32_t uA  = u0;
    uint32_t uBh = u0 + 2 * STAGE_B;
    uint32_t uBl = u0 + 4 * STAGE_B;

    float acc[4][4][4];
#pragma unroll
    for (int i = 0; i < 4; i++)
#pragma unroll
        for (int j = 0; j < 4; j++)
#pragma unroll
            for (int c = 0; c < 4; c++) acc[i][j][c] = 0.f;

    uint32_t aOff = (uint32_t)((wm * 64 + (lane & 15)) * SSTRB + (lane >> 4) * 16);
    uint32_t bOff = (uint32_t)((wn * 32 + (lane & 7) + ((lane >> 4) & 1) * 8) * SSTRB
                               + ((lane >> 3) & 1) * 16);

    auto issue = [&](int st) {
        uint32_t sb = (uint32_t)((st & 1) * STAGE_B);
        int k0 = st * 64;
#pragma unroll
        for (int u = 0; u < 4; u++) {
            int f = tid + 256 * u;
            int row = f >> 3, seg = (f & 7) * 8;
            uint32_t so = sb + (uint32_t)(row * SSTR + seg) * 2;
            size_t g = (size_t)row * D_MODEL + k0 + seg;
            cp16(uA  + so, Ag  + g);
            cp16(uBh + so, Bhg + g);
            cp16(uBl + so, Blg + g);
        }
        CP_COMMIT();
    };

    issue(0);

    for (int st = 0; st < NST; st++) {
        uint32_t sOff = (uint32_t)((st & 1) * STAGE_B);
        CP_WAIT0();
        __syncthreads();               // stage st visible; all warps done with st-1
        if (st < NST - 1) issue(st + 1);

#pragma unroll
        for (int ks = 0; ks < 4; ks++) {
            uint32_t kb = (uint32_t)(ks * 32);
            uint32_t bh[2][4], bl[2][4];
#pragma unroll
            for (int p = 0; p < 2; p++) {
                uint32_t o = sOff + bOff + p * 16 * SSTRB + kb;
                ldsm_x4(bh[p], uBh + o);
                ldsm_x4(bl[p], uBl + o);
            }
#pragma unroll
            for (int mt = 0; mt < 4; mt++) {
                uint32_t ah[4];
                ldsm_x4(ah, uA + sOff + aOff + mt * 16 * SSTRB + kb);
#pragma unroll
                for (int nt = 0; nt < 4; nt++) {
                    int p = nt >> 1, q = (nt & 1) * 2;
                    mma_f16(acc[mt][nt], ah, bh[p][q], bh[p][q + 1]);
                    mma_f16(acc[mt][nt], ah, bl[p][q], bl[p][q + 1]);
                }
            }
        }
    }

    // Epilogue
#pragma unroll
    for (int mt = 0; mt < 4; mt++)
#pragma unroll
        for (int nt = 0; nt < 4; nt++) {
            int row0 = rowBase + wm * 64 + mt * 16 + (lane >> 2);
            int col  = colBase + wn * 32 + nt * 8 + (lane & 3) * 2;
#pragma unroll
            for (int cp = 0; cp < 2; cp++) {
                int row = row0 + cp * 8;
                float v0 = acc[mt][nt][cp * 2], v1 = acc[mt][nt][cp * 2 + 1];
                if (MODE == 1) {
                    *(float2*)(outp + (size_t)row * D_MODEL + col) = make_float2(v0, v1);
                } else {
                    int z = blockIdx.z;
                    if (z == 0) { v0 *= 0.125f; v1 *= 0.125f; }
                    int b = row >> 11, s = row & 2047;
                    int h = col >> 6, d = col & 63;
                    size_t idx = ((size_t)(b * NUM_HEADS + h) * SEQ + s) * DK + d;
                    __half h0 = __float2half_rn(v0), h1 = __float2half_rn(v1);
                    __half* dh = (z == 0) ? g_Qh : (z == 1) ? g_Kh : g_Vh;
                    *(uint32_t*)(dh + idx) = pack_h(h0, h1);
                    if (z == 1) {      // only K keeps a lo-correction
                        __half l0 = __float2half_rn(v0 - __half2float(h0));
                        __half l1 = __float2half_rn(v1 - __half2float(h1));
                        *(uint32_t*)(g_Kl + idx) = pack_h(l0, l1);
                    }
                }
            }
        }
}

// ---------------------------------------------------------------------------
// Flash attention, fp16 asymmetric split, V single:
//   S = Qh*(Kh+Kl)  (2 mma);  O += Ph*Vh  (1 mma)
// CTA: 128 q rows, 8 warps, K-tile 64, cp.async 2-stage K/V, 1 sync/tile,
// 2 CTA/SM.
// ---------------------------------------------------------------------------
#define FSTR  72                      // smem row stride (halves)
#define FSTRB 144
#define FQ_ELE (128 * FSTR)           // 9216 halves
#define FQB    (FQ_ELE * 2)           // 18432 bytes
#define FK_ELE (64 * FSTR)            // 4608 halves
#define FKB    (FK_ELE * 2)           // 9216 bytes per array per stage
#define FL_SMEM (FQB + 6 * FKB)       // 73728 bytes: Kh(2) + Kl(2) + Vh(2)
#define NKT    (SEQ / 64)             // 32 k-tiles

__global__ __launch_bounds__(256, 2) void flash_mma(const int* __restrict__ am)
{
    extern __shared__ __half sb[];
    __shared__ int msk[2][64];

    int tid = threadIdx.x;
    int wid = tid >> 5, lane = tid & 31;
    int g = lane >> 2, tig = lane & 3;
    int q0 = blockIdx.x * 128;
    int h  = blockIdx.y;
    int b  = blockIdx.z;

    size_t hoff = ((size_t)(b * NUM_HEADS + h) * SEQ) * DK;

    uint32_t uB  = smem_to_u32(sb);
    uint32_t uQ  = uB;
    uint32_t uKh = uB + FQB;
    uint32_t uKl = uKh + 2 * FKB;
    uint32_t uVh = uKh + 4 * FKB;
    uint32_t umsk = smem_to_u32(msk);

    const __half* Khg = g_Kh + hoff;
    const __half* Klg = g_Kl + hoff;
    const __half* Vhg = g_Vh + hoff;

    auto issueKV = [&](int kt) {
        uint32_t sbyte = (uint32_t)((kt & 1) * FKB);
        size_t k0d = (size_t)(kt * 64) * DK;
#pragma unroll
        for (int u = 0; u < 2; u++) {
            int f = tid + 256 * u;
            int row = f >> 3, seg = (f & 7) * 8;
            uint32_t so = sbyte + (uint32_t)(row * FSTR + seg) * 2;
            size_t go = k0d + (size_t)row * DK + seg;
            cp16(uKh + so, Khg + go);
            cp16(uKl + so, Klg + go);
            cp16(uVh + so, Vhg + go);
        }
        if (tid < 64)
            cp4(umsk + (uint32_t)(((kt & 1) * 64 + tid) * 4),
                am + (size_t)b * SEQ + kt * 64 + tid);
        CP_COMMIT();
    };

    issueKV(0);

    // Load Q (single fp16, 128 rows x 64 halves) behind the first K/V fetch.
    const __half* Qg = g_Qh + hoff + (size_t)q0 * DK;
    {
        int row = tid >> 1, seg = (tid & 1) * 32;
        *(uint4*)(sb + row * FSTR + seg)      = *(const uint4*)(Qg + (size_t)row * DK + seg);
        *(uint4*)(sb + row * FSTR + seg + 8)  = *(const uint4*)(Qg + (size_t)row * DK + seg + 8);
        *(uint4*)(sb + row * FSTR + seg + 16) = *(const uint4*)(Qg + (size_t)row * DK + seg + 16);
        *(uint4*)(sb + row * FSTR + seg + 24) = *(const uint4*)(Qg + (size_t)row * DK + seg + 24);
    }
    __syncthreads();

    uint32_t qOff = (uint32_t)((wid * 16 + (lane & 15)) * FSTRB + (lane >> 4) * 16);
    uint32_t qh[4][4];
#pragma unroll
    for (int kst = 0; kst < 4; kst++)
        ldsm_x4(qh[kst], uQ + qOff + kst * 32);

    float oacc[8][4];
#pragma unroll
    for (int nt = 0; nt < 8; nt++)
#pragma unroll
        for (int c = 0; c < 4; c++) oacc[nt][c] = 0.f;
    float mrow[2] = {-1e30f, -1e30f}, lrow[2] = {0.f, 0.f};

    uint32_t bOffK = (uint32_t)(((lane & 7) + ((lane >> 4) & 1) * 8) * FSTRB + ((lane >> 3) & 1) * 16);
    uint32_t vOff  = (uint32_t)((lane & 15) * FSTRB + (lane >> 4) * 16);

    for (int kt = 0; kt < NKT; kt++) {
        int stage = kt & 1;
        CP_WAIT0();
        __syncthreads();          // stage kt visible; all warps done with buffer kt-1
        if (kt < NKT - 1) issueKV(kt + 1);

        uint32_t skh = uKh + stage * FKB, skl = uKl + stage * FKB;
        uint32_t svh = uVh + stage * FKB;

        // ----- S = Qh (Kh + Kl)^T -----
        float s[8][4];
#pragma unroll
        for (int nt = 0; nt < 8; nt++)
#pragma unroll
            for (int c = 0; c < 4; c++) s[nt][c] = 0.f;

#pragma unroll
        for (int p = 0; p < 4; p++) {
#pragma unroll
            for (int kst = 0; kst < 4; kst++) {
                uint32_t kh[4], kl[4];
                uint32_t o = p * 16 * FSTRB + kst * 32 + bOffK;
                ldsm_x4(kh, skh + o);
                ldsm_x4(kl, skl + o);
                int nt0 = 2 * p, nt1 = 2 * p + 1;
                mma_f16(s[nt0], qh[kst], kh[0], kh[1]);
                mma_f16(s[nt0], qh[kst], kl[0], kl[1]);
                mma_f16(s[nt1], qh[kst], kh[2], kh[3]);
                mma_f16(s[nt1], qh[kst], kl[2], kl[3]);
            }
        }

        // ----- mask -----
#pragma unroll
        for (int nt = 0; nt < 8; nt++) {
            int c0 = nt * 8 + tig * 2;
            if (msk[stage][c0] == 0)     { s[nt][0] = -1e30f; s[nt][2] = -1e30f; }
            if (msk[stage][c0 + 1] == 0) { s[nt][1] = -1e30f; s[nt][3] = -1e30f; }
        }

        // ----- online softmax (rows g and g+8) -----
        float mx0 = -1e30f, mx1 = -1e30f;
#pragma unroll
        for (int nt = 0; nt < 8; nt++) {
            mx0 = fmaxf(mx0, fmaxf(s[nt][0], s[nt][1]));
            mx1 = fmaxf(mx1, fmaxf(s[nt][2], s[nt][3]));
        }
#pragma unroll
        for (int o = 1; o <= 2; o <<= 1) {
            mx0 = fmaxf(mx0, __shfl_xor_sync(0xffffffffu, mx0, o));
            mx1 = fmaxf(mx1, __shfl_xor_sync(0xffffffffu, mx1, o));
        }
        float mn0 = fmaxf(mrow[0], mx0), mn1 = fmaxf(mrow[1], mx1);
        float al0 = __expf(mrow[0] - mn0), al1 = __expf(mrow[1] - mn1);
        float rs0 = 0.f, rs1 = 0.f;
#pragma unroll
        for (int nt = 0; nt < 8; nt++) {
            s[nt][0] = __expf(s[nt][0] - mn0); rs0 += s[nt][0];
            s[nt][1] = __expf(s[nt][1] - mn0); rs0 += s[nt][1];
            s[nt][2] = __expf(s[nt][2] - mn1); rs1 += s[nt][2];
            s[nt][3] = __expf(s[nt][3] - mn1); rs1 += s[nt][3];
        }
#pragma unroll
        for (int o = 1; o <= 2; o <<= 1) {
            rs0 += __shfl_xor_sync(0xffffffffu, rs0, o);
            rs1 += __shfl_xor_sync(0xffffffffu, rs1, o);
        }
        lrow[0] = lrow[0] * al0 + rs0;  mrow[0] = mn0;
        lrow[1] = lrow[1] * al1 + rs1;  mrow[1] = mn1;
#pragma unroll
        for (int nt = 0; nt < 8; nt++) {
            oacc[nt][0] *= al0; oacc[nt][1] *= al0;
            oacc[nt][2] *= al1; oacc[nt][3] *= al1;
        }

        // ----- P -> single-fp16 A-fragments -----
        uint32_t pa[4][4];
#pragma unroll
        for (int kc = 0; kc < 4; kc++) {
            const float* t0 = s[2 * kc];
            const float* t1 = s[2 * kc + 1];
            pa[kc][0] = pack_h(__float2half_rn(t0[0]), __float2half_rn(t0[1]));
            pa[kc][1] = pack_h(__float2half_rn(t0[2]), __float2half_rn(t0[3]));
            pa[kc][2] = pack_h(__float2half_rn(t1[0]), __float2half_rn(t1[1]));
            pa[kc][3] = pack_h(__float2half_rn(t1[2]), __float2half_rn(t1[3]));
        }

        // ----- O += P Vh (single) -----
#pragma unroll
        for (int kc = 0; kc < 4; kc++) {
            uint32_t vh[4][4];
#pragma unroll
            for (int p = 0; p < 4; p++) {
                uint32_t o = kc * 16 * FSTRB + p * 32 + vOff;
                ldsm_x4_t(vh[p], svh + o);
            }
#pragma unroll
            for (int nt = 0; nt < 8; nt++) {
                int p = nt >> 1, q = (nt & 1) * 2;
                mma_f16(oacc[nt], pa[kc], vh[p][q], vh[p][q + 1]);
            }
        }
    }

    // ----- epilogue: normalize, single-fp16 write to g_AOh -----
    float inv0 = (lrow[0] > 0.f) ? (1.f / lrow[0]) : 0.f;
    float inv1 = (lrow[1] > 0.f) ? (1.f / lrow[1]) : 0.f;
    int r0 = q0 + wid * 16 + g;
    int r1 = r0 + 8;
#pragma unroll
    for (int nt = 0; nt < 8; nt++) {
        int d0 = nt * 8 + tig * 2;
        size_t i0 = ((size_t)b * SEQ + r0) * D_MODEL + h * DK + d0;
        size_t i1 = ((size_t)b * SEQ + r1) * D_MODEL + h * DK + d0;
        *(uint32_t*)(g_AOh + i0) = pack_h(__float2half_rn(oacc[nt][0] * inv0),
                                          __float2half_rn(oacc[nt][1] * inv0));
        *(uint32_t*)(g_AOh + i1) = pack_h(__float2half_rn(oacc[nt][2] * inv1),
                                          __float2half_rn(oacc[nt][3] * inv1));
    }
}

// ---------------------------------------------------------------------------
// Launch
// ---------------------------------------------------------------------------
extern "C" void kernel_launch(void* const* d_in, const int* in_sizes, int n_in,
                              void* d_out, int out_size)
{
    const float* x  = (const float*)d_in[0];
    const int*   am = (const int*)d_in[1];
    const float* Wq = (const float*)d_in[2];
    const float* Wk = (const float*)d_in[3];
    const float* Wv = (const float*)d_in[4];
    const float* Wo = (const float*)d_in[5];
    float* out = (float*)d_out;

    cudaFuncSetAttribute(gemm_mma<0>, cudaFuncAttributeMaxDynamicSharedMemorySize, GEMM_SMEM);
    cudaFuncSetAttribute(gemm_mma<1>, cudaFuncAttributeMaxDynamicSharedMemorySize, GEMM_SMEM);
    cudaFuncSetAttribute(flash_mma, cudaFuncAttributeMaxDynamicSharedMemorySize, FL_SMEM);

    dim3 gc(1024, 5);
    cvt_all<<<gc, 256>>>(x, Wq, Wk, Wv, Wo);

    dim3 gq(D_MODEL / 128, NROWS / 128, 3);     // (8, 32, 3)
    gemm_mma<0><<<gq, 256, GEMM_SMEM>>>(nullptr);

    dim3 ga(SEQ / 128, NUM_HEADS, BATCH);       // (16, 16, 2)
    flash_mma<<<ga, 256, FL_SMEM>>>(am);

    dim3 go(D_MODEL / 128, NROWS / 128, 1);     // (8, 32)
    gemm_mma<1><<<go, 256, GEMM_SMEM>>>(out);
}

// round 16
// speedup vs baseline: 1.6827x; 1.3562x over previous
#include <cuda_runtime.h>
#include <cuda_fp16.h>
#include <cstdint>
#include <math.h>

// Problem constants
#define D_MODEL   1024
#define NUM_HEADS 16
#define DK        64
#define BATCH     2
#define SEQ       2048
#define NROWS     (BATCH * SEQ)      // 4096
#define NX        (NROWS * D_MODEL)  // 4194304
#define NW        (D_MODEL * D_MODEL)// 1048576

// ---------------------------------------------------------------------------
// Scratch (device globals: allocation-free rule)
// All attention operands single fp16; only W_o keeps an fp16 lo-correction
// (its product lands directly in the fp32 output).
// ---------------------------------------------------------------------------
__device__ __half g_xh[NX];                        // x single fp16
__device__ __half g_Wh[4 * NW];                    // Wq,Wk,Wv,Wo hi
__device__ __half g_Wol[NW];                       // Wo lo only
__device__ __half g_Qh[NX];                        // [b][h][s][d], pre-scaled 0.125
__device__ __half g_Kh[NX];
__device__ __half g_Vh[NX];
__device__ __half g_AOh[NX];                       // attn out single [b][s][h*64+d]

// ---------------------------------------------------------------------------
// PTX helpers (plain sm_100-safe: ldmatrix, mma.sync f16, cp.async)
// ---------------------------------------------------------------------------
__device__ __forceinline__ uint32_t smem_to_u32(const void* p) {
    uint32_t a;
    asm("{ .reg .u64 t; cvta.to.shared.u64 t, %1; cvt.u32.u64 %0, t; }" : "=r"(a) : "l"(p));
    return a;
}
__device__ __forceinline__ void ldsm_x4(uint32_t* r, uint32_t addr) {
    asm volatile("ldmatrix.sync.aligned.m8n8.x4.shared.b16 {%0,%1,%2,%3}, [%4];"
        : "=r"(r[0]), "=r"(r[1]), "=r"(r[2]), "=r"(r[3]) : "r"(addr));
}
__device__ __forceinline__ void ldsm_x4_t(uint32_t* r, uint32_t addr) {
    asm volatile("ldmatrix.sync.aligned.m8n8.x4.trans.shared.b16 {%0,%1,%2,%3}, [%4];"
        : "=r"(r[0]), "=r"(r[1]), "=r"(r[2]), "=r"(r[3]) : "r"(addr));
}
__device__ __forceinline__ void mma_f16(float* d, const uint32_t* a, uint32_t b0, uint32_t b1) {
    asm volatile("mma.sync.aligned.m16n8k16.row.col.f32.f16.f16.f32 "
        "{%0,%1,%2,%3}, {%4,%5,%6,%7}, {%8,%9}, {%0,%1,%2,%3};"
        : "+f"(d[0]), "+f"(d[1]), "+f"(d[2]), "+f"(d[3])
        : "r"(a[0]), "r"(a[1]), "r"(a[2]), "r"(a[3]), "r"(b0), "r"(b1));
}
__device__ __forceinline__ void cp16(uint32_t dst, const void* src) {
    asm volatile("cp.async.cg.shared.global [%0], [%1], 16;" :: "r"(dst), "l"(src));
}
__device__ __forceinline__ void cp4(uint32_t dst, const void* src) {
    asm volatile("cp.async.ca.shared.global [%0], [%1], 4;" :: "r"(dst), "l"(src));
}
#define CP_COMMIT() asm volatile("cp.async.commit_group;" ::: "memory")
#define CP_WAIT0()  asm volatile("cp.async.wait_group 0;" ::: "memory")

__device__ __forceinline__ uint32_t pack_h(__half a, __half b) {
    __half2 t = __halves2half2(a, b);
    return *(uint32_t*)&t;
}

// ---------------------------------------------------------------------------
// Pre-pass: convert x + 4 weights to fp16 hi; lo only for Wo (y==4).
// ---------------------------------------------------------------------------
__global__ __launch_bounds__(256) void cvt_all(
    const float* __restrict__ x,  const float* __restrict__ wq,
    const float* __restrict__ wk, const float* __restrict__ wv,
    const float* __restrict__ wo)
{
    int y = blockIdx.y;
    const float* s = (y == 0) ? x : (y == 1) ? wq : (y == 2) ? wk : (y == 3) ? wv : wo;
    __half* dh = (y == 0) ? g_xh : g_Wh + (size_t)(y - 1) * NW;
    size_t n = (y == 0) ? (size_t)NX : (size_t)NW;
    size_t stride = (size_t)gridDim.x * 256 * 4;
    for (size_t i = ((size_t)blockIdx.x * 256 + threadIdx.x) * 4; i < n; i += stride) {
        float4 v = *(const float4*)(s + i);
        float f[4] = {v.x, v.y, v.z, v.w};
        __half h[4];
#pragma unroll
        for (int e = 0; e < 4; e++) h[e] = __float2half_rn(f[e]);
        *(uint2*)(dh + i) = make_uint2(pack_h(h[0], h[1]), pack_h(h[2], h[3]));
        if (y == 4) {
            __half l[4];
#pragma unroll
            for (int e = 0; e < 4; e++)
                l[e] = __float2half_rn(f[e] - __half2float(h[e]));
            *(uint2*)(g_Wol + i) = make_uint2(pack_h(l[0], l[1]), pack_h(l[2], l[3]));
        }
    }
}

// ---------------------------------------------------------------------------
// fp16 tensor-core GEMM. CTA 128x128, 8 warps (2m x 4n), k-stage 64,
// cp.async 2-stage, 1 sync/stage, 2 CTA/SM.
// MODE 0: QKV proj, B single (W-hi), 1 mma/k16; epilogue -> Q/K/V single fp16.
// MODE 1: O-proj, B split (Wo hi+lo), 2 mma/k16; fp32 epilogue to out.
// ---------------------------------------------------------------------------
#define SSTR 72                        // smem row stride in halves (64 data + 8 pad)
#define SSTRB 144
#define STAGE_B   (128 * SSTR * 2)     // 18432 bytes per array per stage
#define GEMM_SMEM0 (4 * STAGE_B)       // 73728:  A(2) + Bh(2)
#define GEMM_SMEM1 (6 * STAGE_B)       // 110592: A(2) + Bh(2) + Bl(2)
#define NST       (D_MODEL / 64)       // 16 k-stages

template<int MODE>
__global__ __launch_bounds__(256, 2) void gemm_mma(float* __restrict__ outp)
{
    extern __shared__ __half ds[];

    int tid = threadIdx.x;
    int wid = tid >> 5, lane = tid & 31;
    int wm = wid & 1, wn = wid >> 1;
    int rowBase = blockIdx.y * 128, colBase = blockIdx.x * 128;

    const __half *Ag, *Bhg, *Blg = nullptr;
    if (MODE == 0) {
        int z = blockIdx.z;
        Ag = g_xh;
        Bhg = g_Wh + (size_t)z * NW;
    } else {
        Ag = g_AOh;
        Bhg = g_Wh + 3ull * NW;
        Blg = g_Wol;
    }
    Ag  += (size_t)rowBase * D_MODEL;
    Bhg += (size_t)colBase * D_MODEL;
    if (MODE == 1) Blg += (size_t)colBase * D_MODEL;

    uint32_t u0  = smem_to_u32(ds);
    uint32_t uA  = u0;
    uint32_t uBh = u0 + 2 * STAGE_B;
    uint32_t uBl = u0 + 4 * STAGE_B;   // MODE 1 only

    float acc[4][4][4];
#pragma unroll
    for (int i = 0; i < 4; i++)
#pragma unroll
        for (int j = 0; j < 4; j++)
#pragma unroll
            for (int c = 0; c < 4; c++) acc[i][j][c] = 0.f;

    uint32_t aOff = (uint32_t)((wm * 64 + (lane & 15)) * SSTRB + (lane >> 4) * 16);
    uint32_t bOff = (uint32_t)((wn * 32 + (lane & 7) + ((lane >> 4) & 1) * 8) * SSTRB
                               + ((lane >> 3) & 1) * 16);

    auto issue = [&](int st) {
        uint32_t sb = (uint32_t)((st & 1) * STAGE_B);
        int k0 = st * 64;
#pragma unroll
        for (int u = 0; u < 4; u++) {
            int f = tid + 256 * u;
            int row = f >> 3, seg = (f & 7) * 8;
            uint32_t so = sb + (uint32_t)(row * SSTR + seg) * 2;
            size_t g = (size_t)row * D_MODEL + k0 + seg;
            cp16(uA  + so, Ag  + g);
            cp16(uBh + so, Bhg + g);
            if (MODE == 1) cp16(uBl + so, Blg + g);
        }
        CP_COMMIT();
    };

    issue(0);

    for (int st = 0; st < NST; st++) {
        uint32_t sOff = (uint32_t)((st & 1) * STAGE_B);
        CP_WAIT0();
        __syncthreads();               // stage st visible; all warps done with st-1
        if (st < NST - 1) issue(st + 1);

#pragma unroll
        for (int ks = 0; ks < 4; ks++) {
            uint32_t kb = (uint32_t)(ks * 32);
            uint32_t bh[2][4], bl[2][4];
#pragma unroll
            for (int p = 0; p < 2; p++) {
                uint32_t o = sOff + bOff + p * 16 * SSTRB + kb;
                ldsm_x4(bh[p], uBh + o);
                if (MODE == 1) ldsm_x4(bl[p], uBl + o);
            }
#pragma unroll
            for (int mt = 0; mt < 4; mt++) {
                uint32_t ah[4];
                ldsm_x4(ah, uA + sOff + aOff + mt * 16 * SSTRB + kb);
#pragma unroll
                for (int nt = 0; nt < 4; nt++) {
                    int p = nt >> 1, q = (nt & 1) * 2;
                    mma_f16(acc[mt][nt], ah, bh[p][q], bh[p][q + 1]);
                    if (MODE == 1)
                        mma_f16(acc[mt][nt], ah, bl[p][q], bl[p][q + 1]);
                }
            }
        }
    }

    // Epilogue
#pragma unroll
    for (int mt = 0; mt < 4; mt++)
#pragma unroll
        for (int nt = 0; nt < 4; nt++) {
            int row0 = rowBase + wm * 64 + mt * 16 + (lane >> 2);
            int col  = colBase + wn * 32 + nt * 8 + (lane & 3) * 2;
#pragma unroll
            for (int cp = 0; cp < 2; cp++) {
                int row = row0 + cp * 8;
                float v0 = acc[mt][nt][cp * 2], v1 = acc[mt][nt][cp * 2 + 1];
                if (MODE == 1) {
                    *(float2*)(outp + (size_t)row * D_MODEL + col) = make_float2(v0, v1);
                } else {
                    int z = blockIdx.z;
                    if (z == 0) { v0 *= 0.125f; v1 *= 0.125f; }
                    int b = row >> 11, s = row & 2047;
                    int h = col >> 6, d = col & 63;
                    size_t idx = ((size_t)(b * NUM_HEADS + h) * SEQ + s) * DK + d;
                    __half* dh = (z == 0) ? g_Qh : (z == 1) ? g_Kh : g_Vh;
                    *(uint32_t*)(dh + idx) = pack_h(__float2half_rn(v0), __float2half_rn(v1));
                }
            }
        }
}

// ---------------------------------------------------------------------------
// Flash attention, all-single fp16 operands:
//   S = Qh*Kh (1 mma);  O += Ph*Vh (1 mma)
// CTA: 128 q rows, 8 warps, K-tile 64, cp.async 2-stage K/V, 1 sync/tile,
// 2 CTA/SM.
// ---------------------------------------------------------------------------
#define FSTR  72                      // smem row stride (halves)
#define FSTRB 144
#define FQ_ELE (128 * FSTR)           // 9216 halves
#define FQB    (FQ_ELE * 2)           // 18432 bytes
#define FK_ELE (64 * FSTR)            // 4608 halves
#define FKB    (FK_ELE * 2)           // 9216 bytes per array per stage
#define FL_SMEM (FQB + 4 * FKB)       // 55296 bytes: Kh(2) + Vh(2)
#define NKT    (SEQ / 64)             // 32 k-tiles

__global__ __launch_bounds__(256, 2) void flash_mma(const int* __restrict__ am)
{
    extern __shared__ __half sb[];
    __shared__ int msk[2][64];

    int tid = threadIdx.x;
    int wid = tid >> 5, lane = tid & 31;
    int g = lane >> 2, tig = lane & 3;
    int q0 = blockIdx.x * 128;
    int h  = blockIdx.y;
    int b  = blockIdx.z;

    size_t hoff = ((size_t)(b * NUM_HEADS + h) * SEQ) * DK;

    uint32_t uB  = smem_to_u32(sb);
    uint32_t uQ  = uB;
    uint32_t uKh = uB + FQB;
    uint32_t uVh = uKh + 2 * FKB;
    uint32_t umsk = smem_to_u32(msk);

    const __half* Khg = g_Kh + hoff;
    const __half* Vhg = g_Vh + hoff;

    auto issueKV = [&](int kt) {
        uint32_t sbyte = (uint32_t)((kt & 1) * FKB);
        size_t k0d = (size_t)(kt * 64) * DK;
#pragma unroll
        for (int u = 0; u < 2; u++) {
            int f = tid + 256 * u;
            int row = f >> 3, seg = (f & 7) * 8;
            uint32_t so = sbyte + (uint32_t)(row * FSTR + seg) * 2;
            size_t go = k0d + (size_t)row * DK + seg;
            cp16(uKh + so, Khg + go);
            cp16(uVh + so, Vhg + go);
        }
        if (tid < 64)
            cp4(umsk + (uint32_t)(((kt & 1) * 64 + tid) * 4),
                am + (size_t)b * SEQ + kt * 64 + tid);
        CP_COMMIT();
    };

    issueKV(0);

    // Load Q (single fp16, 128 rows x 64 halves) behind the first K/V fetch.
    const __half* Qg = g_Qh + hoff + (size_t)q0 * DK;
    {
        int row = tid >> 1, seg = (tid & 1) * 32;
        *(uint4*)(sb + row * FSTR + seg)      = *(const uint4*)(Qg + (size_t)row * DK + seg);
        *(uint4*)(sb + row * FSTR + seg + 8)  = *(const uint4*)(Qg + (size_t)row * DK + seg + 8);
        *(uint4*)(sb + row * FSTR + seg + 16) = *(const uint4*)(Qg + (size_t)row * DK + seg + 16);
        *(uint4*)(sb + row * FSTR + seg + 24) = *(const uint4*)(Qg + (size_t)row * DK + seg + 24);
    }
    __syncthreads();

    uint32_t qOff = (uint32_t)((wid * 16 + (lane & 15)) * FSTRB + (lane >> 4) * 16);
    uint32_t qh[4][4];
#pragma unroll
    for (int kst = 0; kst < 4; kst++)
        ldsm_x4(qh[kst], uQ + qOff + kst * 32);

    float oacc[8][4];
#pragma unroll
    for (int nt = 0; nt < 8; nt++)
#pragma unroll
        for (int c = 0; c < 4; c++) oacc[nt][c] = 0.f;
    float mrow[2] = {-1e30f, -1e30f}, lrow[2] = {0.f, 0.f};

    uint32_t bOffK = (uint32_t)(((lane & 7) + ((lane >> 4) & 1) * 8) * FSTRB + ((lane >> 3) & 1) * 16);
    uint32_t vOff  = (uint32_t)((lane & 15) * FSTRB + (lane >> 4) * 16);

    for (int kt = 0; kt < NKT; kt++) {
        int stage = kt & 1;
        CP_WAIT0();
        __syncthreads();          // stage kt visible; all warps done with buffer kt-1
        if (kt < NKT - 1) issueKV(kt + 1);

        uint32_t skh = uKh + stage * FKB;
        uint32_t svh = uVh + stage * FKB;

        // ----- S = Qh Kh^T (single) -----
        float s[8][4];
#pragma unroll
        for (int nt = 0; nt < 8; nt++)
#pragma unroll
            for (int c = 0; c < 4; c++) s[nt][c] = 0.f;

#pragma unroll
        for (int p = 0; p < 4; p++) {
#pragma unroll
            for (int kst = 0; kst < 4; kst++) {
                uint32_t kh[4];
                uint32_t o = p * 16 * FSTRB + kst * 32 + bOffK;
                ldsm_x4(kh, skh + o);
                mma_f16(s[2 * p],     qh[kst], kh[0], kh[1]);
                mma_f16(s[2 * p + 1], qh[kst], kh[2], kh[3]);
            }
        }

        // ----- mask -----
#pragma unroll
        for (int nt = 0; nt < 8; nt++) {
            int c0 = nt * 8 + tig * 2;
            if (msk[stage][c0] == 0)     { s[nt][0] = -1e30f; s[nt][2] = -1e30f; }
            if (msk[stage][c0 + 1] == 0) { s[nt][1] = -1e30f; s[nt][3] = -1e30f; }
        }

        // ----- online softmax (rows g and g+8) -----
        float mx0 = -1e30f, mx1 = -1e30f;
#pragma unroll
        for (int nt = 0; nt < 8; nt++) {
            mx0 = fmaxf(mx0, fmaxf(s[nt][0], s[nt][1]));
            mx1 = fmaxf(mx1, fmaxf(s[nt][2], s[nt][3]));
        }
#pragma unroll
        for (int o = 1; o <= 2; o <<= 1) {
            mx0 = fmaxf(mx0, __shfl_xor_sync(0xffffffffu, mx0, o));
            mx1 = fmaxf(mx1, __shfl_xor_sync(0xffffffffu, mx1, o));
        }
        float mn0 = fmaxf(mrow[0], mx0), mn1 = fmaxf(mrow[1], mx1);
        float al0 = __expf(mrow[0] - mn0), al1 = __expf(mrow[1] - mn1);
        float rs0 = 0.f, rs1 = 0.f;
#pragma unroll
        for (int nt = 0; nt < 8; nt++) {
            s[nt][0] = __expf(s[nt][0] - mn0); rs0 += s[nt][0];
            s[nt][1] = __expf(s[nt][1] - mn0); rs0 += s[nt][1];
            s[nt][2] = __expf(s[nt][2] - mn1); rs1 += s[nt][2];
            s[nt][3] = __expf(s[nt][3] - mn1); rs1 += s[nt][3];
        }
#pragma unroll
        for (int o = 1; o <= 2; o <<= 1) {
            rs0 += __shfl_xor_sync(0xffffffffu, rs0, o);
            rs1 += __shfl_xor_sync(0xffffffffu, rs1, o);
        }
        lrow[0] = lrow[0] * al0 + rs0;  mrow[0] = mn0;
        lrow[1] = lrow[1] * al1 + rs1;  mrow[1] = mn1;
#pragma unroll
        for (int nt = 0; nt < 8; nt++) {
            oacc[nt][0] *= al0; oacc[nt][1] *= al0;
            oacc[nt][2] *= al1; oacc[nt][3] *= al1;
        }

        // ----- P -> single-fp16 A-fragments -----
        uint32_t pa[4][4];
#pragma unroll
        for (int kc = 0; kc < 4; kc++) {
            const float* t0 = s[2 * kc];
            const float* t1 = s[2 * kc + 1];
            pa[kc][0] = pack_h(__float2half_rn(t0[0]), __float2half_rn(t0[1]));
            pa[kc][1] = pack_h(__float2half_rn(t0[2]), __float2half_rn(t0[3]));
            pa[kc][2] = pack_h(__float2half_rn(t1[0]), __float2half_rn(t1[1]));
            pa[kc][3] = pack_h(__float2half_rn(t1[2]), __float2half_rn(t1[3]));
        }

        // ----- O += P Vh (single) -----
#pragma unroll
        for (int kc = 0; kc < 4; kc++) {
            uint32_t vh[4][4];
#pragma unroll
            for (int p = 0; p < 4; p++) {
                uint32_t o = kc * 16 * FSTRB + p * 32 + vOff;
                ldsm_x4_t(vh[p], svh + o);
            }
#pragma unroll
            for (int nt = 0; nt < 8; nt++) {
                int p = nt >> 1, q = (nt & 1) * 2;
                mma_f16(oacc[nt], pa[kc], vh[p][q], vh[p][q + 1]);
            }
        }
    }

    // ----- epilogue: normalize, single-fp16 write to g_AOh -----
    float inv0 = (lrow[0] > 0.f) ? (1.f / lrow[0]) : 0.f;
    float inv1 = (lrow[1] > 0.f) ? (1.f / lrow[1]) : 0.f;
    int r0 = q0 + wid * 16 + g;
    int r1 = r0 + 8;
#pragma unroll
    for (int nt = 0; nt < 8; nt++) {
        int d0 = nt * 8 + tig * 2;
        size_t i0 = ((size_t)b * SEQ + r0) * D_MODEL + h * DK + d0;
        size_t i1 = ((size_t)b * SEQ + r1) * D_MODEL + h * DK + d0;
        *(uint32_t*)(g_AOh + i0) = pack_h(__float2half_rn(oacc[nt][0] * inv0),
                                          __float2half_rn(oacc[nt][1] * inv0));
        *(uint32_t*)(g_AOh + i1) = pack_h(__float2half_rn(oacc[nt][2] * inv1),
                                          __float2half_rn(oacc[nt][3] * inv1));
    }
}

// ---------------------------------------------------------------------------
// Launch
// ---------------------------------------------------------------------------
extern "C" void kernel_launch(void* const* d_in, const int* in_sizes, int n_in,
                              void* d_out, int out_size)
{
    const float* x  = (const float*)d_in[0];
    const int*   am = (const int*)d_in[1];
    const float* Wq = (const float*)d_in[2];
    const float* Wk = (const float*)d_in[3];
    const float* Wv = (const float*)d_in[4];
    const float* Wo = (const float*)d_in[5];
    float* out = (float*)d_out;

    cudaFuncSetAttribute(gemm_mma<0>, cudaFuncAttributeMaxDynamicSharedMemorySize, GEMM_SMEM0);
    cudaFuncSetAttribute(gemm_mma<1>, cudaFuncAttributeMaxDynamicSharedMemorySize, GEMM_SMEM1);
    cudaFuncSetAttribute(flash_mma, cudaFuncAttributeMaxDynamicSharedMemorySize, FL_SMEM);

    dim3 gc(1024, 5);
    cvt_all<<<gc, 256>>>(x, Wq, Wk, Wv, Wo);

    dim3 gq(D_MODEL / 128, NROWS / 128, 3);     // (8, 32, 3)
    gemm_mma<0><<<gq, 256, GEMM_SMEM0>>>(nullptr);

    dim3 ga(SEQ / 128, NUM_HEADS, BATCH);       // (16, 16, 2)
    flash_mma<<<ga, 256, FL_SMEM>>>(am);

    dim3 go(D_MODEL / 128, NROWS / 128, 1);     // (8, 32)
    gemm_mma<1><<<go, 256, GEMM_SMEM1>>>(out);
}

// round 17
// speedup vs baseline: 1.8129x; 1.0774x over previous
#include <cuda_runtime.h>
#include <cuda_fp16.h>
#include <cstdint>
#include <math.h>

// Problem constants
#define D_MODEL   1024
#define NUM_HEADS 16
#define DK        64
#define BATCH     2
#define SEQ       2048
#define NROWS     (BATCH * SEQ)      // 4096
#define NX        (NROWS * D_MODEL)  // 4194304
#define NW        (D_MODEL * D_MODEL)// 1048576

// ---------------------------------------------------------------------------
// Scratch (device globals: allocation-free rule)
// All operands single fp16 (error budget measured: rel_err ~6.5e-4 < 1e-3).
// ---------------------------------------------------------------------------
__device__ __half g_xh[NX];                        // x single fp16
__device__ __half g_Wh[4 * NW];                    // Wq,Wk,Wv,Wo hi
__device__ __half g_Qh[NX];                        // [b][h][s][d], pre-scaled 0.125
__device__ __half g_Kh[NX];
__device__ __half g_Vh[NX];
__device__ __half g_AOh[NX];                       // attn out single [b][s][h*64+d]

// ---------------------------------------------------------------------------
// PTX helpers (plain sm_100-safe: ldmatrix, mma.sync f16, cp.async)
// ---------------------------------------------------------------------------
__device__ __forceinline__ uint32_t smem_to_u32(const void* p) {
    uint32_t a;
    asm("{ .reg .u64 t; cvta.to.shared.u64 t, %1; cvt.u32.u64 %0, t; }" : "=r"(a) : "l"(p));
    return a;
}
__device__ __forceinline__ void ldsm_x4(uint32_t* r, uint32_t addr) {
    asm volatile("ldmatrix.sync.aligned.m8n8.x4.shared.b16 {%0,%1,%2,%3}, [%4];"
        : "=r"(r[0]), "=r"(r[1]), "=r"(r[2]), "=r"(r[3]) : "r"(addr));
}
__device__ __forceinline__ void ldsm_x4_t(uint32_t* r, uint32_t addr) {
    asm volatile("ldmatrix.sync.aligned.m8n8.x4.trans.shared.b16 {%0,%1,%2,%3}, [%4];"
        : "=r"(r[0]), "=r"(r[1]), "=r"(r[2]), "=r"(r[3]) : "r"(addr));
}
__device__ __forceinline__ void mma_f16(float* d, const uint32_t* a, uint32_t b0, uint32_t b1) {
    asm volatile("mma.sync.aligned.m16n8k16.row.col.f32.f16.f16.f32 "
        "{%0,%1,%2,%3}, {%4,%5,%6,%7}, {%8,%9}, {%0,%1,%2,%3};"
        : "+f"(d[0]), "+f"(d[1]), "+f"(d[2]), "+f"(d[3])
        : "r"(a[0]), "r"(a[1]), "r"(a[2]), "r"(a[3]), "r"(b0), "r"(b1));
}
__device__ __forceinline__ void cp16(uint32_t dst, const void* src) {
    asm volatile("cp.async.cg.shared.global [%0], [%1], 16;" :: "r"(dst), "l"(src));
}
__device__ __forceinline__ void cp4(uint32_t dst, const void* src) {
    asm volatile("cp.async.ca.shared.global [%0], [%1], 4;" :: "r"(dst), "l"(src));
}
#define CP_COMMIT() asm volatile("cp.async.commit_group;" ::: "memory")
#define CP_WAIT0()  asm volatile("cp.async.wait_group 0;" ::: "memory")

__device__ __forceinline__ uint32_t pack_h(__half a, __half b) {
    __half2 t = __halves2half2(a, b);
    return *(uint32_t*)&t;
}

// ---------------------------------------------------------------------------
// Pre-pass: convert x + 4 weights to single fp16.
// ---------------------------------------------------------------------------
__global__ __launch_bounds__(256) void cvt_all(
    const float* __restrict__ x,  const float* __restrict__ wq,
    const float* __restrict__ wk, const float* __restrict__ wv,
    const float* __restrict__ wo)
{
    int y = blockIdx.y;
    const float* s = (y == 0) ? x : (y == 1) ? wq : (y == 2) ? wk : (y == 3) ? wv : wo;
    __half* dh = (y == 0) ? g_xh : g_Wh + (size_t)(y - 1) * NW;
    size_t n = (y == 0) ? (size_t)NX : (size_t)NW;
    size_t stride = (size_t)gridDim.x * 256 * 4;
    for (size_t i = ((size_t)blockIdx.x * 256 + threadIdx.x) * 4; i < n; i += stride) {
        float4 v = *(const float4*)(s + i);
        __half h[4] = {__float2half_rn(v.x), __float2half_rn(v.y),
                       __float2half_rn(v.z), __float2half_rn(v.w)};
        *(uint2*)(dh + i) = make_uint2(pack_h(h[0], h[1]), pack_h(h[2], h[3]));
    }
}

// ---------------------------------------------------------------------------
// fp16 tensor-core GEMM (single-precision operands, 1 mma/k16).
// CTA 128x128, 8 warps (2m x 4n), k-stage 64, cp.async 2-stage,
// 1 sync/stage, 2 CTA/SM.
// MODE 0: QKV proj (z selects W; epilogue -> Q(x0.125)/K/V single fp16)
// MODE 1: O-proj (A = g_AOh, B = Wo-hi; fp32 epilogue to out)
// ---------------------------------------------------------------------------
#define SSTR 72                        // smem row stride in halves (64 data + 8 pad)
#define SSTRB 144
#define STAGE_B   (128 * SSTR * 2)     // 18432 bytes per array per stage
#define GEMM_SMEM (4 * STAGE_B)        // 73728: A(2) + B(2)
#define NST       (D_MODEL / 64)       // 16 k-stages

template<int MODE>
__global__ __launch_bounds__(256, 2) void gemm_mma(float* __restrict__ outp)
{
    extern __shared__ __half ds[];

    int tid = threadIdx.x;
    int wid = tid >> 5, lane = tid & 31;
    int wm = wid & 1, wn = wid >> 1;
    int rowBase = blockIdx.y * 128, colBase = blockIdx.x * 128;

    const __half *Ag, *Bg;
    if (MODE == 0) {
        Ag = g_xh;
        Bg = g_Wh + (size_t)blockIdx.z * NW;
    } else {
        Ag = g_AOh;
        Bg = g_Wh + 3ull * NW;
    }
    Ag += (size_t)rowBase * D_MODEL;
    Bg += (size_t)colBase * D_MODEL;

    uint32_t u0 = smem_to_u32(ds);
    uint32_t uA = u0;
    uint32_t uB = u0 + 2 * STAGE_B;

    float acc[4][4][4];
#pragma unroll
    for (int i = 0; i < 4; i++)
#pragma unroll
        for (int j = 0; j < 4; j++)
#pragma unroll
            for (int c = 0; c < 4; c++) acc[i][j][c] = 0.f;

    uint32_t aOff = (uint32_t)((wm * 64 + (lane & 15)) * SSTRB + (lane >> 4) * 16);
    uint32_t bOff = (uint32_t)((wn * 32 + (lane & 7) + ((lane >> 4) & 1) * 8) * SSTRB
                               + ((lane >> 3) & 1) * 16);

    auto issue = [&](int st) {
        uint32_t sb = (uint32_t)((st & 1) * STAGE_B);
        int k0 = st * 64;
#pragma unroll
        for (int u = 0; u < 4; u++) {
            int f = tid + 256 * u;
            int row = f >> 3, seg = (f & 7) * 8;
            uint32_t so = sb + (uint32_t)(row * SSTR + seg) * 2;
            size_t g = (size_t)row * D_MODEL + k0 + seg;
            cp16(uA + so, Ag + g);
            cp16(uB + so, Bg + g);
        }
        CP_COMMIT();
    };

    issue(0);

    for (int st = 0; st < NST; st++) {
        uint32_t sOff = (uint32_t)((st & 1) * STAGE_B);
        CP_WAIT0();
        __syncthreads();               // stage st visible; all warps done with st-1
        if (st < NST - 1) issue(st + 1);

#pragma unroll
        for (int ks = 0; ks < 4; ks++) {
            uint32_t kb = (uint32_t)(ks * 32);
            uint32_t bh[2][4];
#pragma unroll
            for (int p = 0; p < 2; p++)
                ldsm_x4(bh[p], uB + sOff + bOff + p * 16 * SSTRB + kb);
#pragma unroll
            for (int mt = 0; mt < 4; mt++) {
                uint32_t ah[4];
                ldsm_x4(ah, uA + sOff + aOff + mt * 16 * SSTRB + kb);
#pragma unroll
                for (int nt = 0; nt < 4; nt++) {
                    int p = nt >> 1, q = (nt & 1) * 2;
                    mma_f16(acc[mt][nt], ah, bh[p][q], bh[p][q + 1]);
                }
            }
        }
    }

    // Epilogue
#pragma unroll
    for (int mt = 0; mt < 4; mt++)
#pragma unroll
        for (int nt = 0; nt < 4; nt++) {
            int row0 = rowBase + wm * 64 + mt * 16 + (lane >> 2);
            int col  = colBase + wn * 32 + nt * 8 + (lane & 3) * 2;
#pragma unroll
            for (int cp = 0; cp < 2; cp++) {
                int row = row0 + cp * 8;
                float v0 = acc[mt][nt][cp * 2], v1 = acc[mt][nt][cp * 2 + 1];
                if (MODE == 1) {
                    *(float2*)(outp + (size_t)row * D_MODEL + col) = make_float2(v0, v1);
                } else {
                    int z = blockIdx.z;
                    if (z == 0) { v0 *= 0.125f; v1 *= 0.125f; }
                    int b = row >> 11, s = row & 2047;
                    int h = col >> 6, d = col & 63;
                    size_t idx = ((size_t)(b * NUM_HEADS + h) * SEQ + s) * DK + d;
                    __half* dh = (z == 0) ? g_Qh : (z == 1) ? g_Kh : g_Vh;
                    *(uint32_t*)(dh + idx) = pack_h(__float2half_rn(v0), __float2half_rn(v1));
                }
            }
        }
}

// ---------------------------------------------------------------------------
// Flash attention, all-single fp16 operands:
//   S = Qh*Kh (1 mma);  O += Ph*Vh (1 mma)
// CTA: 128 q rows, 8 warps, K-tile 64, cp.async 2-stage K/V, 1 sync/tile,
// 2 CTA/SM.
// ---------------------------------------------------------------------------
#define FSTR  72                      // smem row stride (halves)
#define FSTRB 144
#define FQ_ELE (128 * FSTR)           // 9216 halves
#define FQB    (FQ_ELE * 2)           // 18432 bytes
#define FK_ELE (64 * FSTR)            // 4608 halves
#define FKB    (FK_ELE * 2)           // 9216 bytes per array per stage
#define FL_SMEM (FQB + 4 * FKB)       // 55296 bytes: Kh(2) + Vh(2)
#define NKT    (SEQ / 64)             // 32 k-tiles

__global__ __launch_bounds__(256, 2) void flash_mma(const int* __restrict__ am)
{
    extern __shared__ __half sb[];
    __shared__ int msk[2][64];

    int tid = threadIdx.x;
    int wid = tid >> 5, lane = tid & 31;
    int g = lane >> 2, tig = lane & 3;
    int q0 = blockIdx.x * 128;
    int h  = blockIdx.y;
    int b  = blockIdx.z;

    size_t hoff = ((size_t)(b * NUM_HEADS + h) * SEQ) * DK;

    uint32_t uB  = smem_to_u32(sb);
    uint32_t uQ  = uB;
    uint32_t uKh = uB + FQB;
    uint32_t uVh = uKh + 2 * FKB;
    uint32_t umsk = smem_to_u32(msk);

    const __half* Khg = g_Kh + hoff;
    const __half* Vhg = g_Vh + hoff;

    auto issueKV = [&](int kt) {
        uint32_t sbyte = (uint32_t)((kt & 1) * FKB);
        size_t k0d = (size_t)(kt * 64) * DK;
#pragma unroll
        for (int u = 0; u < 2; u++) {
            int f = tid + 256 * u;
            int row = f >> 3, seg = (f & 7) * 8;
            uint32_t so = sbyte + (uint32_t)(row * FSTR + seg) * 2;
            size_t go = k0d + (size_t)row * DK + seg;
            cp16(uKh + so, Khg + go);
            cp16(uVh + so, Vhg + go);
        }
        if (tid < 64)
            cp4(umsk + (uint32_t)(((kt & 1) * 64 + tid) * 4),
                am + (size_t)b * SEQ + kt * 64 + tid);
        CP_COMMIT();
    };

    issueKV(0);

    // Load Q (single fp16, 128 rows x 64 halves) behind the first K/V fetch.
    const __half* Qg = g_Qh + hoff + (size_t)q0 * DK;
    {
        int row = tid >> 1, seg = (tid & 1) * 32;
        *(uint4*)(sb + row * FSTR + seg)      = *(const uint4*)(Qg + (size_t)row * DK + seg);
        *(uint4*)(sb + row * FSTR + seg + 8)  = *(const uint4*)(Qg + (size_t)row * DK + seg + 8);
        *(uint4*)(sb + row * FSTR + seg + 16) = *(const uint4*)(Qg + (size_t)row * DK + seg + 16);
        *(uint4*)(sb + row * FSTR + seg + 24) = *(const uint4*)(Qg + (size_t)row * DK + seg + 24);
    }
    __syncthreads();

    uint32_t qOff = (uint32_t)((wid * 16 + (lane & 15)) * FSTRB + (lane >> 4) * 16);
    uint32_t qh[4][4];
#pragma unroll
    for (int kst = 0; kst < 4; kst++)
        ldsm_x4(qh[kst], uQ + qOff + kst * 32);

    float oacc[8][4];
#pragma unroll
    for (int nt = 0; nt < 8; nt++)
#pragma unroll
        for (int c = 0; c < 4; c++) oacc[nt][c] = 0.f;
    float mrow[2] = {-1e30f, -1e30f}, lrow[2] = {0.f, 0.f};

    uint32_t bOffK = (uint32_t)(((lane & 7) + ((lane >> 4) & 1) * 8) * FSTRB + ((lane >> 3) & 1) * 16);
    uint32_t vOff  = (uint32_t)((lane & 15) * FSTRB + (lane >> 4) * 16);

    for (int kt = 0; kt < NKT; kt++) {
        int stage = kt & 1;
        CP_WAIT0();
        __syncthreads();          // stage kt visible; all warps done with buffer kt-1
        if (kt < NKT - 1) issueKV(kt + 1);

        uint32_t skh = uKh + stage * FKB;
        uint32_t svh = uVh + stage * FKB;

        // ----- S = Qh Kh^T (single) -----
        float s[8][4];
#pragma unroll
        for (int nt = 0; nt < 8; nt++)
#pragma unroll
            for (int c = 0; c < 4; c++) s[nt][c] = 0.f;

#pragma unroll
        for (int p = 0; p < 4; p++) {
#pragma unroll
            for (int kst = 0; kst < 4; kst++) {
                uint32_t kh[4];
                uint32_t o = p * 16 * FSTRB + kst * 32 + bOffK;
                ldsm_x4(kh, skh + o);
                mma_f16(s[2 * p],     qh[kst], kh[0], kh[1]);
                mma_f16(s[2 * p + 1], qh[kst], kh[2], kh[3]);
            }
        }

        // ----- mask -----
#pragma unroll
        for (int nt = 0; nt < 8; nt++) {
            int c0 = nt * 8 + tig * 2;
            if (msk[stage][c0] == 0)     { s[nt][0] = -1e30f; s[nt][2] = -1e30f; }
            if (msk[stage][c0 + 1] == 0) { s[nt][1] = -1e30f; s[nt][3] = -1e30f; }
        }

        // ----- online softmax (rows g and g+8) -----
        float mx0 = -1e30f, mx1 = -1e30f;
#pragma unroll
        for (int nt = 0; nt < 8; nt++) {
            mx0 = fmaxf(mx0, fmaxf(s[nt][0], s[nt][1]));
            mx1 = fmaxf(mx1, fmaxf(s[nt][2], s[nt][3]));
        }
#pragma unroll
        for (int o = 1; o <= 2; o <<= 1) {
            mx0 = fmaxf(mx0, __shfl_xor_sync(0xffffffffu, mx0, o));
            mx1 = fmaxf(mx1, __shfl_xor_sync(0xffffffffu, mx1, o));
        }
        float mn0 = fmaxf(mrow[0], mx0), mn1 = fmaxf(mrow[1], mx1);
        float al0 = __expf(mrow[0] - mn0), al1 = __expf(mrow[1] - mn1);
        float rs0 = 0.f, rs1 = 0.f;
#pragma unroll
        for (int nt = 0; nt < 8; nt++) {
            s[nt][0] = __expf(s[nt][0] - mn0); rs0 += s[nt][0];
            s[nt][1] = __expf(s[nt][1] - mn0); rs0 += s[nt][1];
            s[nt][2] = __expf(s[nt][2] - mn1); rs1 += s[nt][2];
            s[nt][3] = __expf(s[nt][3] - mn1); rs1 += s[nt][3];
        }
#pragma unroll
        for (int o = 1; o <= 2; o <<= 1) {
            rs0 += __shfl_xor_sync(0xffffffffu, rs0, o);
            rs1 += __shfl_xor_sync(0xffffffffu, rs1, o);
        }
        lrow[0] = lrow[0] * al0 + rs0;  mrow[0] = mn0;
        lrow[1] = lrow[1] * al1 + rs1;  mrow[1] = mn1;
#pragma unroll
        for (int nt = 0; nt < 8; nt++) {
            oacc[nt][0] *= al0; oacc[nt][1] *= al0;
            oacc[nt][2] *= al1; oacc[nt][3] *= al1;
        }

        // ----- P -> single-fp16 A-fragments -----
        uint32_t pa[4][4];
#pragma unroll
        for (int kc = 0; kc < 4; kc++) {
            const float* t0 = s[2 * kc];
            const float* t1 = s[2 * kc + 1];
            pa[kc][0] = pack_h(__float2half_rn(t0[0]), __float2half_rn(t0[1]));
            pa[kc][1] = pack_h(__float2half_rn(t0[2]), __float2half_rn(t0[3]));
            pa[kc][2] = pack_h(__float2half_rn(t1[0]), __float2half_rn(t1[1]));
            pa[kc][3] = pack_h(__float2half_rn(t1[2]), __float2half_rn(t1[3]));
        }

        // ----- O += P Vh (single) -----
#pragma unroll
        for (int kc = 0; kc < 4; kc++) {
            uint32_t vh[4][4];
#pragma unroll
            for (int p = 0; p < 4; p++) {
                uint32_t o = kc * 16 * FSTRB + p * 32 + vOff;
                ldsm_x4_t(vh[p], svh + o);
            }
#pragma unroll
            for (int nt = 0; nt < 8; nt++) {
                int p = nt >> 1, q = (nt & 1) * 2;
                mma_f16(oacc[nt], pa[kc], vh[p][q], vh[p][q + 1]);
            }
        }
    }

    // ----- epilogue: normalize, single-fp16 write to g_AOh -----
    float inv0 = (lrow[0] > 0.f) ? (1.f / lrow[0]) : 0.f;
    float inv1 = (lrow[1] > 0.f) ? (1.f / lrow[1]) : 0.f;
    int r0 = q0 + wid * 16 + g;
    int r1 = r0 + 8;
#pragma unroll
    for (int nt = 0; nt < 8; nt++) {
        int d0 = nt * 8 + tig * 2;
        size_t i0 = ((size_t)b * SEQ + r0) * D_MODEL + h * DK + d0;
        size_t i1 = ((size_t)b * SEQ + r1) * D_MODEL + h * DK + d0;
        *(uint32_t*)(g_AOh + i0) = pack_h(__float2half_rn(oacc[nt][0] * inv0),
                                          __float2half_rn(oacc[nt][1] * inv0));
        *(uint32_t*)(g_AOh + i1) = pack_h(__float2half_rn(oacc[nt][2] * inv1),
                                          __float2half_rn(oacc[nt][3] * inv1));
    }
}

// ---------------------------------------------------------------------------
// Launch
// ---------------------------------------------------------------------------
extern "C" void kernel_launch(void* const* d_in, const int* in_sizes, int n_in,
                              void* d_out, int out_size)
{
    const float* x  = (const float*)d_in[0];
    const int*   am = (const int*)d_in[1];
    const float* Wq = (const float*)d_in[2];
    const float* Wk = (const float*)d_in[3];
    const float* Wv = (const float*)d_in[4];
    const float* Wo = (const float*)d_in[5];
    float* out = (float*)d_out;

    cudaFuncSetAttribute(gemm_mma<0>, cudaFuncAttributeMaxDynamicSharedMemorySize, GEMM_SMEM);
    cudaFuncSetAttribute(gemm_mma<1>, cudaFuncAttributeMaxDynamicSharedMemorySize, GEMM_SMEM);
    cudaFuncSetAttribute(flash_mma, cudaFuncAttributeMaxDynamicSharedMemorySize, FL_SMEM);

    dim3 gc(1024, 5);
    cvt_all<<<gc, 256>>>(x, Wq, Wk, Wv, Wo);

    dim3 gq(D_MODEL / 128, NROWS / 128, 3);     // (8, 32, 3)
    gemm_mma<0><<<gq, 256, GEMM_SMEM>>>(nullptr);

    dim3 ga(SEQ / 128, NUM_HEADS, BATCH);       // (16, 16, 2)
    flash_mma<<<ga, 256, FL_SMEM>>>(am);

    dim3 go(D_MODEL / 128, NROWS / 128, 1);     // (8, 32)
    gemm_mma<1><<<go, 256, GEMM_SMEM>>>(out);
}